// round 13
// baseline (speedup 1.0000x reference)
#include <cuda_runtime.h>
#include <math.h>

// ---------------- scratch (device globals; no allocation allowed) ----------
#define OFF_LIG     0           // 512*128
#define OFF_POC     65536       // 1024*128
#define OFF_M       196608      // 512*1024
#define OFF_MT      720896      // 1024*512
#define OFF_AGGL    1245184     // 512*128
#define OFF_AGGP    1310720     // 1024*128
#define OFF_LIGE    1441792     // 512*128
#define OFF_POCE    1507328     // 1024*128
#define OFF_QKVL    1638400     // 512*384
#define OFF_QKVP    1835008     // 1024*384
#define OFF_ATTL    2228224     // 512*128
#define OFF_ATTP    2293760     // 1024*128
#define OFF_TAB     2424832     // 4096
#define SCRATCH_FLOATS 2428928

__device__ float g_scratch[SCRATCH_FLOATS];

#define TAB_N 4096
#define D_MAX 35.0f

// ---------------- f32x2 helpers ----------------------------------------------
__device__ __forceinline__ unsigned long long fma2(unsigned long long a,
                                                   unsigned long long b,
                                                   unsigned long long c) {
    unsigned long long d;
    asm("fma.rn.f32x2 %0, %1, %2, %3;" : "=l"(d) : "l"(a), "l"(b), "l"(c));
    return d;
}
__device__ __forceinline__ unsigned long long mul2(unsigned long long a,
                                                   unsigned long long b) {
    unsigned long long d;
    asm("mul.rn.f32x2 %0, %1, %2;" : "=l"(d) : "l"(a), "l"(b));
    return d;
}
__device__ __forceinline__ unsigned long long add2(unsigned long long a,
                                                   unsigned long long b) {
    unsigned long long d;
    asm("add.rn.f32x2 %0, %1, %2;" : "=l"(d) : "l"(a), "l"(b));
    return d;
}
__device__ __forceinline__ unsigned long long pack2(float x, float y) {
    unsigned long long r;
    asm("mov.b64 %0, {%1, %2};" : "=l"(r) : "f"(x), "f"(y));
    return r;
}
__device__ __forceinline__ void unpack2(unsigned long long v, float& x, float& y) {
    asm("mov.b64 {%0, %1}, %2;" : "=f"(x), "=f"(y) : "l"(v));
}
__device__ __forceinline__ float hsum2(unsigned long long v) {
    float x, y;
    unpack2(v, x, y);
    return x + y;
}

// ---------------- k_pre: 208 blocks x 256 (2 subtiles) -------------------------
__global__ void __launch_bounds__(256) k_pre(const float* __restrict__ Wd1,
                                             const float* __restrict__ bd1,
                                             const float* __restrict__ Wd2,
                                             const float* __restrict__ bd2,
                                             const float* __restrict__ Wd3,
                                             const float* __restrict__ bd3,
                                             float* __restrict__ tab,
                                             const float* __restrict__ lf,
                                             const float* __restrict__ pf,
                                             const float* __restrict__ Wl,
                                             const float* __restrict__ bl,
                                             const float* __restrict__ Wp,
                                             const float* __restrict__ bp,
                                             float* __restrict__ lig,
                                             float* __restrict__ poc) {
    __shared__ __align__(16) float smem[2 * 2304];
    int tid = threadIdx.x;
    int sub = tid >> 7, st = tid & 127;
    int vb = blockIdx.x * 2 + sub;
    float* sbuf = smem + sub * 2304;
    float* w1s = sbuf + 2048;
    float* b1s = w1s + 32;
    float* b2s = b1s + 32;
    float* wms = b2s + 64;
    float* mcs = wms + 64;

    if (vb < 32) {
        for (int idx = st; idx < 2048; idx += 128) sbuf[idx] = Wd2[idx];
        if (st < 32) { w1s[st] = Wd1[st]; b1s[st] = bd1[st]; }
        if (st >= 32 && st < 96) b2s[st - 32] = bd2[st - 32];
        if (st < 64) {
            float s = 0.f;
            for (int i = 0; i < 128; i++) s += Wd3[i * 64 + st];
            wms[st] = s * (1.f / 128.f);
        }
        if (st == 127) {
            float s = 0.f;
            for (int i = 0; i < 128; i++) s += bd3[i];
            *mcs = s * (1.f / 128.f);
        }
        __syncthreads();
        int idx = vb * 128 + st;
        float d = (float)idx * (D_MAX / (float)(TAB_N - 1));
        float h1[32];
        #pragma unroll
        for (int k = 0; k < 32; k++) h1[k] = fmaxf(fmaf(d, w1s[k], b1s[k]), 0.f);
        float mval = *mcs;
        #pragma unroll 1
        for (int j = 0; j < 64; j++) {
            const float4* wr = (const float4*)(sbuf + j * 32);
            float a0 = 0.f, a1 = 0.f, a2 = 0.f, a3 = 0.f;
            #pragma unroll
            for (int q = 0; q < 8; q++) {
                float4 w = wr[q];
                a0 = fmaf(w.x, h1[4 * q + 0], a0);
                a1 = fmaf(w.y, h1[4 * q + 1], a1);
                a2 = fmaf(w.z, h1[4 * q + 2], a2);
                a3 = fmaf(w.w, h1[4 * q + 3], a3);
            }
            float pre = b2s[j] + ((a0 + a1) + (a2 + a3));
            mval = fmaf(fmaxf(pre, 0.f), wms[j], mval);
        }
        tab[idx] = mval;
    } else {
        int pb = vb - 32;
        const float* X; const float* W; const float* B; float* Y; int r0;
        if (pb < 128) { X = lf; W = Wl; B = bl; Y = lig; r0 = pb * 4; }
        else          { X = pf; W = Wp; B = bp; Y = poc; r0 = (pb - 128) * 4; }
        ((float4*)sbuf)[st] = ((const float4*)(X + (size_t)r0 * 128))[st];
        __syncthreads();
        const ulonglong2* X2 = (const ulonglong2*)sbuf;
        const ulonglong2* w2 = (const ulonglong2*)(W + (size_t)st * 128);
        unsigned long long acc2[4] = {0ull, 0ull, 0ull, 0ull};
        #pragma unroll 8
        for (int kb = 0; kb < 32; kb++) {
            ulonglong2 w = w2[kb];
            #pragma unroll
            for (int r = 0; r < 4; r++) {
                ulonglong2 x = X2[r * 32 + kb];
                acc2[r] = fma2(x.x, w.x, acc2[r]);
                acc2[r] = fma2(x.y, w.y, acc2[r]);
            }
        }
        float bv = B[st];
        #pragma unroll
        for (int r = 0; r < 4; r++)
            Y[(size_t)(r0 + r) * 128 + st] = hsum2(acc2[r]) + bv;
    }
}

// ---------------- pair: m via table lerp, write M and MT ----------------------
__global__ void __launch_bounds__(256) k_pairm(const float* __restrict__ lc,
                                               const float* __restrict__ pc,
                                               const float* __restrict__ tab,
                                               float* __restrict__ M,
                                               float* __restrict__ MT) {
    __shared__ float tabs[TAB_N];
    __shared__ float pcs[3072];
    int tid = threadIdx.x;
    for (int idx = tid; idx < TAB_N; idx += 256) tabs[idx] = tab[idx];
    for (int idx = tid; idx < 3072; idx += 256) pcs[idx] = pc[idx];
    __syncthreads();

    int i0 = blockIdx.x * 4;
    float lx[4], ly[4], lz[4];
    #pragma unroll
    for (int r = 0; r < 4; r++) {
        lx[r] = lc[(i0 + r) * 3 + 0];
        ly[r] = lc[(i0 + r) * 3 + 1];
        lz[r] = lc[(i0 + r) * 3 + 2];
    }
    const float invh = (float)(TAB_N - 1) / D_MAX;
    #pragma unroll
    for (int jj = 0; jj < 4; jj++) {
        int j = jj * 256 + tid;
        float px = pcs[j * 3 + 0], py = pcs[j * 3 + 1], pz = pcs[j * 3 + 2];
        float4 v;
        float* vp = (float*)&v;
        #pragma unroll
        for (int r = 0; r < 4; r++) {
            float dx = lx[r] - px, dy = ly[r] - py, dz = lz[r] - pz;
            float d = sqrtf(fmaf(dx, dx, fmaf(dy, dy, dz * dz)));
            float t = d * invh;
            int t0 = min((int)t, TAB_N - 2);
            float f = t - (float)t0;
            float v0 = tabs[t0], v1 = tabs[t0 + 1];
            vp[r] = fmaf(f, v1 - v0, v0);
            M[(size_t)(i0 + r) * 1024 + j] = vp[r];
        }
        *(float4*)(MT + (size_t)j * 512 + i0) = v;
    }
}

// ---------------- agg with fused softmax, register-blocked GEMM ---------------
__global__ void __launch_bounds__(256) k_aggsoft(const float* __restrict__ M,
                                                 const float* __restrict__ MT,
                                                 const float* __restrict__ poc,
                                                 const float* __restrict__ lig,
                                                 float* __restrict__ aggl,
                                                 float* __restrict__ aggp) {
    __shared__ __align__(16) float As[8192];
    int tid = threadIdx.x, bx = blockIdx.x;
    const float* S; const float* B; float* Y; int r0, K;
    if (bx < 64) { S = M;  B = poc; Y = aggl; r0 = bx * 8;        K = 1024; }
    else         { S = MT; B = lig; Y = aggp; r0 = (bx - 64) * 8; K = 512;  }

    int w = tid >> 5, lane = tid & 31;
    const float* srow = S + (size_t)(r0 + w) * K;
    if (K == 1024) {
        float mv[32];
        float mx = -3.4e38f;
        #pragma unroll
        for (int t = 0; t < 32; t++) {
            float v = -srow[t * 32 + lane];
            mv[t] = v;
            mx = fmaxf(mx, v);
        }
        #pragma unroll
        for (int o = 16; o > 0; o >>= 1)
            mx = fmaxf(mx, __shfl_xor_sync(0xffffffffu, mx, o));
        float sum = 0.f;
        #pragma unroll
        for (int t = 0; t < 32; t++) {
            float e = __expf(mv[t] - mx);
            mv[t] = e;
            sum += e;
        }
        #pragma unroll
        for (int o = 16; o > 0; o >>= 1)
            sum += __shfl_xor_sync(0xffffffffu, sum, o);
        float inv = 1.f / sum;
        #pragma unroll
        for (int t = 0; t < 32; t++) As[(t * 32 + lane) * 8 + w] = mv[t] * inv;
    } else {
        float mv[16];
        float mx = -3.4e38f;
        #pragma unroll
        for (int t = 0; t < 16; t++) {
            float v = -srow[t * 32 + lane];
            mv[t] = v;
            mx = fmaxf(mx, v);
        }
        #pragma unroll
        for (int o = 16; o > 0; o >>= 1)
            mx = fmaxf(mx, __shfl_xor_sync(0xffffffffu, mx, o));
        float sum = 0.f;
        #pragma unroll
        for (int t = 0; t < 16; t++) {
            float e = __expf(mv[t] - mx);
            mv[t] = e;
            sum += e;
        }
        #pragma unroll
        for (int o = 16; o > 0; o >>= 1)
            sum += __shfl_xor_sync(0xffffffffu, sum, o);
        float inv = 1.f / sum;
        #pragma unroll
        for (int t = 0; t < 16; t++) As[(t * 32 + lane) * 8 + w] = mv[t] * inv;
    }
    __syncthreads();

    int cg = tid & 31, ks = tid >> 5;
    int steps = K >> 3;
    int kstart = ks * steps;
    float4 acc4[8];
    #pragma unroll
    for (int r = 0; r < 8; r++) acc4[r] = make_float4(0.f, 0.f, 0.f, 0.f);
    const float4* As4 = (const float4*)As;
    const float4* B4 = (const float4*)B;
    #pragma unroll 2
    for (int kk = 0; kk < steps; kk++) {
        int k = kstart + kk;
        float4 a0 = As4[k * 2 + 0];
        float4 a1 = As4[k * 2 + 1];
        float4 b = B4[(size_t)k * 32 + cg];
        acc4[0].x = fmaf(a0.x, b.x, acc4[0].x); acc4[0].y = fmaf(a0.x, b.y, acc4[0].y);
        acc4[0].z = fmaf(a0.x, b.z, acc4[0].z); acc4[0].w = fmaf(a0.x, b.w, acc4[0].w);
        acc4[1].x = fmaf(a0.y, b.x, acc4[1].x); acc4[1].y = fmaf(a0.y, b.y, acc4[1].y);
        acc4[1].z = fmaf(a0.y, b.z, acc4[1].z); acc4[1].w = fmaf(a0.y, b.w, acc4[1].w);
        acc4[2].x = fmaf(a0.z, b.x, acc4[2].x); acc4[2].y = fmaf(a0.z, b.y, acc4[2].y);
        acc4[2].z = fmaf(a0.z, b.z, acc4[2].z); acc4[2].w = fmaf(a0.z, b.w, acc4[2].w);
        acc4[3].x = fmaf(a0.w, b.x, acc4[3].x); acc4[3].y = fmaf(a0.w, b.y, acc4[3].y);
        acc4[3].z = fmaf(a0.w, b.z, acc4[3].z); acc4[3].w = fmaf(a0.w, b.w, acc4[3].w);
        acc4[4].x = fmaf(a1.x, b.x, acc4[4].x); acc4[4].y = fmaf(a1.x, b.y, acc4[4].y);
        acc4[4].z = fmaf(a1.x, b.z, acc4[4].z); acc4[4].w = fmaf(a1.x, b.w, acc4[4].w);
        acc4[5].x = fmaf(a1.y, b.x, acc4[5].x); acc4[5].y = fmaf(a1.y, b.y, acc4[5].y);
        acc4[5].z = fmaf(a1.y, b.z, acc4[5].z); acc4[5].w = fmaf(a1.y, b.w, acc4[5].w);
        acc4[6].x = fmaf(a1.z, b.x, acc4[6].x); acc4[6].y = fmaf(a1.z, b.y, acc4[6].y);
        acc4[6].z = fmaf(a1.z, b.z, acc4[6].z); acc4[6].w = fmaf(a1.z, b.w, acc4[6].w);
        acc4[7].x = fmaf(a1.w, b.x, acc4[7].x); acc4[7].y = fmaf(a1.w, b.y, acc4[7].y);
        acc4[7].z = fmaf(a1.w, b.z, acc4[7].z); acc4[7].w = fmaf(a1.w, b.w, acc4[7].w);
    }
    __syncthreads();
    float4* P4 = (float4*)As;
    #pragma unroll
    for (int r = 0; r < 8; r++) P4[ks * 256 + r * 32 + cg] = acc4[r];
    __syncthreads();
    float4 s = P4[tid];
    #pragma unroll
    for (int sl = 1; sl < 8; sl++) {
        float4 p = P4[sl * 256 + tid];
        s.x += p.x; s.y += p.y; s.z += p.z; s.w += p.w;
    }
    int r = tid >> 5, cc = tid & 31;
    ((float4*)(Y + (size_t)(r0 + r) * 128))[cc] = s;
}

// ---------------- gate: 192 blocks x 256, 8-row tiles, K split in halves ------
__global__ void __launch_bounds__(256) k_gate(const float* __restrict__ lig,
                                              const float* __restrict__ poc,
                                              const float* __restrict__ aggl,
                                              const float* __restrict__ aggp,
                                              const float* __restrict__ Wgl,
                                              const float* __restrict__ bgl,
                                              const float* __restrict__ Wgp,
                                              const float* __restrict__ bgp,
                                              float* __restrict__ lige,
                                              float* __restrict__ poce) {
    __shared__ __align__(16) float xs[1024];
    __shared__ __align__(16) float as_[1024];
    __shared__ float red[1024];
    int tid = threadIdx.x, vb = blockIdx.x;
    const float* X; const float* A; const float* W; const float* B;
    float* Y; int r0;
    if (vb < 64) { X = lig; A = aggl; W = Wgl; B = bgl; Y = lige; r0 = vb * 8; }
    else { X = poc; A = aggp; W = Wgp; B = bgp; Y = poce; r0 = (vb - 64) * 8; }
    ((float4*)xs)[tid] = ((const float4*)(X + (size_t)r0 * 128))[tid];
    ((float4*)as_)[tid] = ((const float4*)(A + (size_t)r0 * 128))[tid];
    __syncthreads();
    int c = tid & 127, part = tid >> 7;
    const ulonglong2* S2 = (const ulonglong2*)(part ? as_ : xs);
    const ulonglong2* w2 = (const ulonglong2*)(W + (size_t)c * 256 + part * 128);
    unsigned long long acc2[8];
    #pragma unroll
    for (int r = 0; r < 8; r++) acc2[r] = 0ull;
    #pragma unroll 8
    for (int kb = 0; kb < 32; kb++) {
        ulonglong2 w = w2[kb];
        #pragma unroll
        for (int r = 0; r < 8; r++) {
            ulonglong2 x = S2[r * 32 + kb];
            acc2[r] = fma2(x.x, w.x, acc2[r]);
            acc2[r] = fma2(x.y, w.y, acc2[r]);
        }
    }
    if (part) {
        #pragma unroll
        for (int r = 0; r < 8; r++) red[c * 8 + r] = hsum2(acc2[r]);
    }
    __syncthreads();
    if (!part) {
        float bv = B[c];
        #pragma unroll
        for (int r = 0; r < 8; r++) {
            float t = hsum2(acc2[r]) + red[c * 8 + r] + bv;
            float g = 1.f / (1.f + __expf(-t));
            float xv = xs[r * 128 + c], av = as_[r * 128 + c];
            Y[(size_t)(r0 + r) * 128 + c] = g * xv + (1.f - g) * av;
        }
    }
}

// ---------------- qkv: 576 blocks x 128, 8-row tiles ---------------------------
__global__ void __launch_bounds__(128) k_qkv(const float* __restrict__ lige,
                                             const float* __restrict__ poce,
                                             const float* __restrict__ W,
                                             const float* __restrict__ B,
                                             float* __restrict__ qkvl,
                                             float* __restrict__ qkvp) {
    __shared__ __align__(16) float Xs[1024];
    int tid = threadIdx.x, vb = blockIdx.x;
    int p = vb / 192, tile = vb % 192;
    const float* X; float* Y; int r0;
    if (tile < 64) { X = lige; Y = qkvl; r0 = tile * 8; }
    else           { X = poce; Y = qkvp; r0 = (tile - 64) * 8; }
    ((float4*)Xs)[tid] = ((const float4*)(X + (size_t)r0 * 128))[tid];
    ((float4*)Xs)[tid + 128] = ((const float4*)(X + (size_t)r0 * 128))[tid + 128];
    __syncthreads();
    const ulonglong2* X2 = (const ulonglong2*)Xs;
    int c = p * 128 + tid;
    const ulonglong2* w2 = (const ulonglong2*)(W + (size_t)c * 128);
    unsigned long long acc2[8] = {0ull, 0ull, 0ull, 0ull, 0ull, 0ull, 0ull, 0ull};
    #pragma unroll 4
    for (int kb = 0; kb < 32; kb++) {
        ulonglong2 w = w2[kb];
        #pragma unroll
        for (int r = 0; r < 8; r++) {
            ulonglong2 x = X2[r * 32 + kb];
            acc2[r] = fma2(x.x, w.x, acc2[r]);
            acc2[r] = fma2(x.y, w.y, acc2[r]);
        }
    }
    float bv = B[c];
    #pragma unroll
    for (int r = 0; r < 8; r++)
        Y[(size_t)(r0 + r) * 384 + c] = hsum2(acc2[r]) + bv;
}

// ---------------- flash attention: 4 queries/warp, f32x2 QK + AV ---------------
// grid(96, 8), block 128 = 4 warps x 4 queries = 16 queries/block.
__global__ void __launch_bounds__(128) k_flash4(const float* __restrict__ qkvl,
                                                const float* __restrict__ qkvp,
                                                float* __restrict__ attl,
                                                float* __restrict__ attp) {
    __shared__ __align__(16) float4 Ks[128 * 5];
    __shared__ __align__(16) float4 Vs[128 * 5];
    int bx = blockIdx.x, h = blockIdx.y;
    int tid = threadIdx.x, w = tid >> 5, lane = tid & 31;
    const float* Qb; const float* KVb; float* outp; int nk, i0;
    if (bx < 32) { Qb = qkvl; KVb = qkvp; outp = attl; nk = 1024; i0 = bx * 16 + w * 4; }
    else         { Qb = qkvp; KVb = qkvl; outp = attp; nk = 512; i0 = (bx - 32) * 16 + w * 4; }

    // packed queries: q[qq][0..7] each holds 2 floats
    unsigned long long q[4][8];
    #pragma unroll
    for (int qq = 0; qq < 4; qq++) {
        const ulonglong2* qp = (const ulonglong2*)(Qb + (size_t)(i0 + qq) * 384 + h * 16);
        #pragma unroll
        for (int u = 0; u < 4; u++) {
            ulonglong2 t = qp[u];
            q[qq][u * 2] = t.x;
            q[qq][u * 2 + 1] = t.y;
        }
    }

    float m[4] = {-3.4e38f, -3.4e38f, -3.4e38f, -3.4e38f};
    float l[4] = {0.f, 0.f, 0.f, 0.f};
    unsigned long long acc[4][8];
    #pragma unroll
    for (int qq = 0; qq < 4; qq++)
        #pragma unroll
        for (int u = 0; u < 8; u++) acc[qq][u] = 0ull;

    const float* kb0 = KVb + (size_t)tid * 384 + 128 + h * 16;

    for (int jb = 0; jb < nk; jb += 128) {
        __syncthreads();
        const float4* src = (const float4*)(kb0 + (size_t)jb * 384);
        Ks[tid * 5 + 0] = src[0]; Ks[tid * 5 + 1] = src[1];
        Ks[tid * 5 + 2] = src[2]; Ks[tid * 5 + 3] = src[3];
        const float4* srcv = (const float4*)(kb0 + (size_t)jb * 384 + 128);
        Vs[tid * 5 + 0] = srcv[0]; Vs[tid * 5 + 1] = srcv[1];
        Vs[tid * 5 + 2] = srcv[2]; Vs[tid * 5 + 3] = srcv[3];
        __syncthreads();

        float s[4][4];   // [jj][qq]
        #pragma unroll
        for (int jj = 0; jj < 4; jj++) {
            const ulonglong2* kr = (const ulonglong2*)(Ks + (jj * 32 + lane) * 5);
            ulonglong2 k01 = kr[0], k23 = kr[1], k45 = kr[2], k67 = kr[3];
            #pragma unroll
            for (int qq = 0; qq < 4; qq++) {
                unsigned long long a = mul2(q[qq][0], k01.x);
                a = fma2(q[qq][1], k01.y, a);
                a = fma2(q[qq][2], k23.x, a);
                a = fma2(q[qq][3], k23.y, a);
                a = fma2(q[qq][4], k45.x, a);
                a = fma2(q[qq][5], k45.y, a);
                a = fma2(q[qq][6], k67.x, a);
                a = fma2(q[qq][7], k67.y, a);
                s[jj][qq] = hsum2(a) * 0.25f;
            }
        }
        #pragma unroll
        for (int qq = 0; qq < 4; qq++) {
            float tmax = fmaxf(fmaxf(s[0][qq], s[1][qq]), fmaxf(s[2][qq], s[3][qq]));
            #pragma unroll
            for (int o = 16; o > 0; o >>= 1)
                tmax = fmaxf(tmax, __shfl_xor_sync(0xffffffffu, tmax, o));
            float mnew = fmaxf(m[qq], tmax);
            float corr = __expf(m[qq] - mnew);
            m[qq] = mnew;
            l[qq] *= corr;
            unsigned long long c2 = pack2(corr, corr);
            #pragma unroll
            for (int u = 0; u < 8; u++) acc[qq][u] = mul2(acc[qq][u], c2);
        }
        #pragma unroll
        for (int jj = 0; jj < 4; jj++) {
            const ulonglong2* vr = (const ulonglong2*)(Vs + (jj * 32 + lane) * 5);
            ulonglong2 v01 = vr[0], v23 = vr[1], v45 = vr[2], v67 = vr[3];
            #pragma unroll
            for (int qq = 0; qq < 4; qq++) {
                float p = __expf(s[jj][qq] - m[qq]);
                l[qq] += p;
                unsigned long long p2 = pack2(p, p);
                acc[qq][0] = fma2(p2, v01.x, acc[qq][0]);
                acc[qq][1] = fma2(p2, v01.y, acc[qq][1]);
                acc[qq][2] = fma2(p2, v23.x, acc[qq][2]);
                acc[qq][3] = fma2(p2, v23.y, acc[qq][3]);
                acc[qq][4] = fma2(p2, v45.x, acc[qq][4]);
                acc[qq][5] = fma2(p2, v45.y, acc[qq][5]);
                acc[qq][6] = fma2(p2, v67.x, acc[qq][6]);
                acc[qq][7] = fma2(p2, v67.y, acc[qq][7]);
            }
        }
    }

    #pragma unroll
    for (int qq = 0; qq < 4; qq++) {
        #pragma unroll
        for (int o = 16; o > 0; o >>= 1)
            l[qq] += __shfl_xor_sync(0xffffffffu, l[qq], o);
        #pragma unroll
        for (int u = 0; u < 8; u++) {
            #pragma unroll
            for (int o = 16; o > 0; o >>= 1)
                acc[qq][u] = add2(acc[qq][u], __shfl_xor_sync(0xffffffffu, acc[qq][u], o));
        }
        if (lane < 16) {
            float x, y;
            unpack2(acc[qq][lane >> 1], x, y);
            float val = (lane & 1) ? y : x;
            outp[(size_t)(i0 + qq) * 128 + h * 16 + lane] = val * (1.f / l[qq]);
        }
    }
}

// ---------------- out-proj + residual + LN: 192 blocks x 128, 8-row tiles -----
__global__ void __launch_bounds__(128) k_outln(const float* __restrict__ attl,
                                               const float* __restrict__ attp,
                                               const float* __restrict__ W,
                                               const float* __restrict__ bias,
                                               const float* __restrict__ lige,
                                               const float* __restrict__ poce,
                                               const float* __restrict__ g_l,
                                               const float* __restrict__ be_l,
                                               const float* __restrict__ g_p,
                                               const float* __restrict__ be_p,
                                               float* __restrict__ out) {
    __shared__ __align__(16) float Xs[1024];
    __shared__ __align__(16) float T[1024];
    __shared__ float mu[8], iv[8];
    int tid = threadIdx.x, vb = blockIdx.x;
    const float* X; const float* R; const float* gg; const float* bb;
    float* O; int r0;
    if (vb < 64) { X = attl; R = lige; gg = g_l; bb = be_l; O = out; r0 = vb * 8; }
    else {
        X = attp; R = poce; gg = g_p; bb = be_p;
        O = out + 512 * 128; r0 = (vb - 64) * 8;
    }
    ((float4*)Xs)[tid] = ((const float4*)(X + (size_t)r0 * 128))[tid];
    ((float4*)Xs)[tid + 128] = ((const float4*)(X + (size_t)r0 * 128))[tid + 128];
    __syncthreads();
    const ulonglong2* X2 = (const ulonglong2*)Xs;
    const ulonglong2* w2 = (const ulonglong2*)(W + (size_t)tid * 128);
    unsigned long long acc2[8] = {0ull, 0ull, 0ull, 0ull, 0ull, 0ull, 0ull, 0ull};
    #pragma unroll 4
    for (int kb = 0; kb < 32; kb++) {
        ulonglong2 w = w2[kb];
        #pragma unroll
        for (int r = 0; r < 8; r++) {
            ulonglong2 x = X2[r * 32 + kb];
            acc2[r] = fma2(x.x, w.x, acc2[r]);
            acc2[r] = fma2(x.y, w.y, acc2[r]);
        }
    }
    float bv = bias[tid];
    #pragma unroll
    for (int r = 0; r < 8; r++)
        T[r * 128 + tid] = hsum2(acc2[r]) + bv + R[(size_t)(r0 + r) * 128 + tid];
    __syncthreads();

    int wrp = tid >> 5, lane = tid & 31;
    #pragma unroll
    for (int rr = 0; rr < 2; rr++) {
        int r = wrp * 2 + rr;
        float t0 = T[r * 128 + lane], t1 = T[r * 128 + lane + 32];
        float t2 = T[r * 128 + lane + 64], t3 = T[r * 128 + lane + 96];
        float s = (t0 + t1) + (t2 + t3);
        #pragma unroll
        for (int o = 16; o > 0; o >>= 1) s += __shfl_xor_sync(0xffffffffu, s, o);
        float mean = s * (1.f / 128.f);
        float d0 = t0 - mean, d1 = t1 - mean, d2 = t2 - mean, d3 = t3 - mean;
        float v = (d0 * d0 + d1 * d1) + (d2 * d2 + d3 * d3);
        #pragma unroll
        for (int o = 16; o > 0; o >>= 1) v += __shfl_xor_sync(0xffffffffu, v, o);
        if (lane == 0) {
            mu[r] = mean;
            iv[r] = rsqrtf(v * (1.f / 128.f) + 1e-5f);
        }
    }
    __syncthreads();
    float gc = gg[tid], bc = bb[tid];
    #pragma unroll
    for (int r = 0; r < 8; r++) {
        float t = T[r * 128 + tid];
        O[(size_t)(r0 + r) * 128 + tid] = (t - mu[r]) * iv[r] * gc + bc;
    }
}

// ---------------- launch ------------------------------------------------------
extern "C" void kernel_launch(void* const* d_in, const int* in_sizes, int n_in,
                              void* d_out, int out_size) {
    const float* lf   = (const float*)d_in[0];
    const float* pf   = (const float*)d_in[1];
    const float* lc   = (const float*)d_in[2];
    const float* pc   = (const float*)d_in[3];
    const float* Wl   = (const float*)d_in[4];
    const float* bl   = (const float*)d_in[5];
    const float* Wp   = (const float*)d_in[6];
    const float* bp   = (const float*)d_in[7];
    const float* Wd1  = (const float*)d_in[8];
    const float* bd1  = (const float*)d_in[9];
    const float* Wd2  = (const float*)d_in[10];
    const float* bd2  = (const float*)d_in[11];
    const float* Wd3  = (const float*)d_in[12];
    const float* bd3  = (const float*)d_in[13];
    const float* Wgl  = (const float*)d_in[14];
    const float* bgl  = (const float*)d_in[15];
    const float* Wgp  = (const float*)d_in[16];
    const float* bgp  = (const float*)d_in[17];
    const float* Wqkv = (const float*)d_in[18];
    const float* bqkv = (const float*)d_in[19];
    const float* Wo   = (const float*)d_in[20];
    const float* bo   = (const float*)d_in[21];
    const float* g_l  = (const float*)d_in[22];
    const float* be_l = (const float*)d_in[23];
    const float* g_p  = (const float*)d_in[24];
    const float* be_p = (const float*)d_in[25];
    float* out = (float*)d_out;

    float* SB = nullptr;
    cudaGetSymbolAddress((void**)&SB, g_scratch);
    float* s_lig  = SB + OFF_LIG;
    float* s_poc  = SB + OFF_POC;
    float* s_m    = SB + OFF_M;
    float* s_mt   = SB + OFF_MT;
    float* s_aggl = SB + OFF_AGGL;
    float* s_aggp = SB + OFF_AGGP;
    float* s_lige = SB + OFF_LIGE;
    float* s_poce = SB + OFF_POCE;
    float* s_qkvl = SB + OFF_QKVL;
    float* s_qkvp = SB + OFF_QKVP;
    float* s_attl = SB + OFF_ATTL;
    float* s_attp = SB + OFF_ATTP;
    float* s_tab  = SB + OFF_TAB;

    k_pre<<<208, 256>>>(Wd1, bd1, Wd2, bd2, Wd3, bd3, s_tab,
                        lf, pf, Wl, bl, Wp, bp, s_lig, s_poc);
    k_pairm<<<128, 256>>>(lc, pc, s_tab, s_m, s_mt);
    k_aggsoft<<<192, 256>>>(s_m, s_mt, s_poc, s_lig, s_aggl, s_aggp);
    k_gate<<<192, 256>>>(s_lig, s_poc, s_aggl, s_aggp, Wgl, bgl, Wgp, bgp,
                         s_lige, s_poce);
    k_qkv<<<576, 128>>>(s_lige, s_poce, Wqkv, bqkv, s_qkvl, s_qkvp);
    k_flash4<<<dim3(96, 8), 128>>>(s_qkvl, s_qkvp, s_attl, s_attp);
    k_outln<<<192, 128>>>(s_attl, s_attp, Wo, bo, s_lige, s_poce,
                          g_l, be_l, g_p, be_p, out);
}

// round 14
// speedup vs baseline: 1.0739x; 1.0739x over previous
#include <cuda_runtime.h>
#include <math.h>

// ---------------- scratch (device globals; no allocation allowed) ----------
#define OFF_LIG     0           // 512*128
#define OFF_POC     65536       // 1024*128
#define OFF_M       196608      // 512*1024
#define OFF_MT      720896      // 1024*512
#define OFF_AGGL    1245184     // 512*128
#define OFF_AGGP    1310720     // 1024*128
#define OFF_LIGE    1441792     // 512*128
#define OFF_POCE    1507328     // 1024*128
#define OFF_QKVL    1638400     // 512*384
#define OFF_QKVP    1835008     // 1024*384
#define OFF_ATTL    2228224     // 512*128
#define OFF_ATTP    2293760     // 1024*128
#define OFF_TAB     2424832     // 4096
#define SCRATCH_FLOATS 2428928

__device__ float g_scratch[SCRATCH_FLOATS];

#define TAB_N 4096
#define D_MAX 35.0f

// ---------------- f32x2 helpers ----------------------------------------------
__device__ __forceinline__ unsigned long long fma2(unsigned long long a,
                                                   unsigned long long b,
                                                   unsigned long long c) {
    unsigned long long d;
    asm("fma.rn.f32x2 %0, %1, %2, %3;" : "=l"(d) : "l"(a), "l"(b), "l"(c));
    return d;
}
__device__ __forceinline__ unsigned long long mul2(unsigned long long a,
                                                   unsigned long long b) {
    unsigned long long d;
    asm("mul.rn.f32x2 %0, %1, %2;" : "=l"(d) : "l"(a), "l"(b));
    return d;
}
__device__ __forceinline__ unsigned long long add2(unsigned long long a,
                                                   unsigned long long b) {
    unsigned long long d;
    asm("add.rn.f32x2 %0, %1, %2;" : "=l"(d) : "l"(a), "l"(b));
    return d;
}
__device__ __forceinline__ unsigned long long pack2(float x, float y) {
    unsigned long long r;
    asm("mov.b64 %0, {%1, %2};" : "=l"(r) : "f"(x), "f"(y));
    return r;
}
__device__ __forceinline__ void unpack2(unsigned long long v, float& x, float& y) {
    asm("mov.b64 {%0, %1}, %2;" : "=f"(x), "=f"(y) : "l"(v));
}
__device__ __forceinline__ float hsum2(unsigned long long v) {
    float x, y;
    unpack2(v, x, y);
    return x + y;
}

// ---------------- k_pre: 208 blocks x 256 (2 subtiles) -------------------------
__global__ void __launch_bounds__(256) k_pre(const float* __restrict__ Wd1,
                                             const float* __restrict__ bd1,
                                             const float* __restrict__ Wd2,
                                             const float* __restrict__ bd2,
                                             const float* __restrict__ Wd3,
                                             const float* __restrict__ bd3,
                                             float* __restrict__ tab,
                                             const float* __restrict__ lf,
                                             const float* __restrict__ pf,
                                             const float* __restrict__ Wl,
                                             const float* __restrict__ bl,
                                             const float* __restrict__ Wp,
                                             const float* __restrict__ bp,
                                             float* __restrict__ lig,
                                             float* __restrict__ poc) {
    __shared__ __align__(16) float smem[2 * 2304];
    int tid = threadIdx.x;
    int sub = tid >> 7, st = tid & 127;
    int vb = blockIdx.x * 2 + sub;
    float* sbuf = smem + sub * 2304;
    float* w1s = sbuf + 2048;
    float* b1s = w1s + 32;
    float* b2s = b1s + 32;
    float* wms = b2s + 64;
    float* mcs = wms + 64;

    if (vb < 32) {
        for (int idx = st; idx < 2048; idx += 128) sbuf[idx] = Wd2[idx];
        if (st < 32) { w1s[st] = Wd1[st]; b1s[st] = bd1[st]; }
        if (st >= 32 && st < 96) b2s[st - 32] = bd2[st - 32];
        if (st < 64) {
            float s = 0.f;
            for (int i = 0; i < 128; i++) s += Wd3[i * 64 + st];
            wms[st] = s * (1.f / 128.f);
        }
        if (st == 127) {
            float s = 0.f;
            for (int i = 0; i < 128; i++) s += bd3[i];
            *mcs = s * (1.f / 128.f);
        }
        __syncthreads();
        int idx = vb * 128 + st;
        float d = (float)idx * (D_MAX / (float)(TAB_N - 1));
        float h1[32];
        #pragma unroll
        for (int k = 0; k < 32; k++) h1[k] = fmaxf(fmaf(d, w1s[k], b1s[k]), 0.f);
        float mval = *mcs;
        #pragma unroll 1
        for (int j = 0; j < 64; j++) {
            const float4* wr = (const float4*)(sbuf + j * 32);
            float a0 = 0.f, a1 = 0.f, a2 = 0.f, a3 = 0.f;
            #pragma unroll
            for (int q = 0; q < 8; q++) {
                float4 w = wr[q];
                a0 = fmaf(w.x, h1[4 * q + 0], a0);
                a1 = fmaf(w.y, h1[4 * q + 1], a1);
                a2 = fmaf(w.z, h1[4 * q + 2], a2);
                a3 = fmaf(w.w, h1[4 * q + 3], a3);
            }
            float pre = b2s[j] + ((a0 + a1) + (a2 + a3));
            mval = fmaf(fmaxf(pre, 0.f), wms[j], mval);
        }
        tab[idx] = mval;
    } else {
        int pb = vb - 32;
        const float* X; const float* W; const float* B; float* Y; int r0;
        if (pb < 128) { X = lf; W = Wl; B = bl; Y = lig; r0 = pb * 4; }
        else          { X = pf; W = Wp; B = bp; Y = poc; r0 = (pb - 128) * 4; }
        ((float4*)sbuf)[st] = ((const float4*)(X + (size_t)r0 * 128))[st];
        __syncthreads();
        const ulonglong2* X2 = (const ulonglong2*)sbuf;
        const ulonglong2* w2 = (const ulonglong2*)(W + (size_t)st * 128);
        unsigned long long acc2[4] = {0ull, 0ull, 0ull, 0ull};
        #pragma unroll 8
        for (int kb = 0; kb < 32; kb++) {
            ulonglong2 w = w2[kb];
            #pragma unroll
            for (int r = 0; r < 4; r++) {
                ulonglong2 x = X2[r * 32 + kb];
                acc2[r] = fma2(x.x, w.x, acc2[r]);
                acc2[r] = fma2(x.y, w.y, acc2[r]);
            }
        }
        float bv = B[st];
        #pragma unroll
        for (int r = 0; r < 4; r++)
            Y[(size_t)(r0 + r) * 128 + st] = hsum2(acc2[r]) + bv;
    }
}

// ---------------- pair: m via table lerp, write M and MT ----------------------
__global__ void __launch_bounds__(256) k_pairm(const float* __restrict__ lc,
                                               const float* __restrict__ pc,
                                               const float* __restrict__ tab,
                                               float* __restrict__ M,
                                               float* __restrict__ MT) {
    __shared__ float tabs[TAB_N];
    __shared__ float pcs[3072];
    int tid = threadIdx.x;
    for (int idx = tid; idx < TAB_N; idx += 256) tabs[idx] = tab[idx];
    for (int idx = tid; idx < 3072; idx += 256) pcs[idx] = pc[idx];
    __syncthreads();

    int i0 = blockIdx.x * 4;
    float lx[4], ly[4], lz[4];
    #pragma unroll
    for (int r = 0; r < 4; r++) {
        lx[r] = lc[(i0 + r) * 3 + 0];
        ly[r] = lc[(i0 + r) * 3 + 1];
        lz[r] = lc[(i0 + r) * 3 + 2];
    }
    const float invh = (float)(TAB_N - 1) / D_MAX;
    #pragma unroll
    for (int jj = 0; jj < 4; jj++) {
        int j = jj * 256 + tid;
        float px = pcs[j * 3 + 0], py = pcs[j * 3 + 1], pz = pcs[j * 3 + 2];
        float4 v;
        float* vp = (float*)&v;
        #pragma unroll
        for (int r = 0; r < 4; r++) {
            float dx = lx[r] - px, dy = ly[r] - py, dz = lz[r] - pz;
            float d = sqrtf(fmaf(dx, dx, fmaf(dy, dy, dz * dz)));
            float t = d * invh;
            int t0 = min((int)t, TAB_N - 2);
            float f = t - (float)t0;
            float v0 = tabs[t0], v1 = tabs[t0 + 1];
            vp[r] = fmaf(f, v1 - v0, v0);
            M[(size_t)(i0 + r) * 1024 + j] = vp[r];
        }
        *(float4*)(MT + (size_t)j * 512 + i0) = v;
    }
}

// ---------------- agg with fused softmax, register-blocked GEMM ---------------
__global__ void __launch_bounds__(256) k_aggsoft(const float* __restrict__ M,
                                                 const float* __restrict__ MT,
                                                 const float* __restrict__ poc,
                                                 const float* __restrict__ lig,
                                                 float* __restrict__ aggl,
                                                 float* __restrict__ aggp) {
    __shared__ __align__(16) float As[8192];
    int tid = threadIdx.x, bx = blockIdx.x;
    const float* S; const float* B; float* Y; int r0, K;
    if (bx < 64) { S = M;  B = poc; Y = aggl; r0 = bx * 8;        K = 1024; }
    else         { S = MT; B = lig; Y = aggp; r0 = (bx - 64) * 8; K = 512;  }

    int w = tid >> 5, lane = tid & 31;
    const float* srow = S + (size_t)(r0 + w) * K;
    if (K == 1024) {
        float mv[32];
        float mx = -3.4e38f;
        #pragma unroll
        for (int t = 0; t < 32; t++) {
            float v = -srow[t * 32 + lane];
            mv[t] = v;
            mx = fmaxf(mx, v);
        }
        #pragma unroll
        for (int o = 16; o > 0; o >>= 1)
            mx = fmaxf(mx, __shfl_xor_sync(0xffffffffu, mx, o));
        float sum = 0.f;
        #pragma unroll
        for (int t = 0; t < 32; t++) {
            float e = __expf(mv[t] - mx);
            mv[t] = e;
            sum += e;
        }
        #pragma unroll
        for (int o = 16; o > 0; o >>= 1)
            sum += __shfl_xor_sync(0xffffffffu, sum, o);
        float inv = 1.f / sum;
        #pragma unroll
        for (int t = 0; t < 32; t++) As[(t * 32 + lane) * 8 + w] = mv[t] * inv;
    } else {
        float mv[16];
        float mx = -3.4e38f;
        #pragma unroll
        for (int t = 0; t < 16; t++) {
            float v = -srow[t * 32 + lane];
            mv[t] = v;
            mx = fmaxf(mx, v);
        }
        #pragma unroll
        for (int o = 16; o > 0; o >>= 1)
            mx = fmaxf(mx, __shfl_xor_sync(0xffffffffu, mx, o));
        float sum = 0.f;
        #pragma unroll
        for (int t = 0; t < 16; t++) {
            float e = __expf(mv[t] - mx);
            mv[t] = e;
            sum += e;
        }
        #pragma unroll
        for (int o = 16; o > 0; o >>= 1)
            sum += __shfl_xor_sync(0xffffffffu, sum, o);
        float inv = 1.f / sum;
        #pragma unroll
        for (int t = 0; t < 16; t++) As[(t * 32 + lane) * 8 + w] = mv[t] * inv;
    }
    __syncthreads();

    int cg = tid & 31, ks = tid >> 5;
    int steps = K >> 3;
    int kstart = ks * steps;
    float4 acc4[8];
    #pragma unroll
    for (int r = 0; r < 8; r++) acc4[r] = make_float4(0.f, 0.f, 0.f, 0.f);
    const float4* As4 = (const float4*)As;
    const float4* B4 = (const float4*)B;
    #pragma unroll 2
    for (int kk = 0; kk < steps; kk++) {
        int k = kstart + kk;
        float4 a0 = As4[k * 2 + 0];
        float4 a1 = As4[k * 2 + 1];
        float4 b = B4[(size_t)k * 32 + cg];
        acc4[0].x = fmaf(a0.x, b.x, acc4[0].x); acc4[0].y = fmaf(a0.x, b.y, acc4[0].y);
        acc4[0].z = fmaf(a0.x, b.z, acc4[0].z); acc4[0].w = fmaf(a0.x, b.w, acc4[0].w);
        acc4[1].x = fmaf(a0.y, b.x, acc4[1].x); acc4[1].y = fmaf(a0.y, b.y, acc4[1].y);
        acc4[1].z = fmaf(a0.y, b.z, acc4[1].z); acc4[1].w = fmaf(a0.y, b.w, acc4[1].w);
        acc4[2].x = fmaf(a0.z, b.x, acc4[2].x); acc4[2].y = fmaf(a0.z, b.y, acc4[2].y);
        acc4[2].z = fmaf(a0.z, b.z, acc4[2].z); acc4[2].w = fmaf(a0.z, b.w, acc4[2].w);
        acc4[3].x = fmaf(a0.w, b.x, acc4[3].x); acc4[3].y = fmaf(a0.w, b.y, acc4[3].y);
        acc4[3].z = fmaf(a0.w, b.z, acc4[3].z); acc4[3].w = fmaf(a0.w, b.w, acc4[3].w);
        acc4[4].x = fmaf(a1.x, b.x, acc4[4].x); acc4[4].y = fmaf(a1.x, b.y, acc4[4].y);
        acc4[4].z = fmaf(a1.x, b.z, acc4[4].z); acc4[4].w = fmaf(a1.x, b.w, acc4[4].w);
        acc4[5].x = fmaf(a1.y, b.x, acc4[5].x); acc4[5].y = fmaf(a1.y, b.y, acc4[5].y);
        acc4[5].z = fmaf(a1.y, b.z, acc4[5].z); acc4[5].w = fmaf(a1.y, b.w, acc4[5].w);
        acc4[6].x = fmaf(a1.z, b.x, acc4[6].x); acc4[6].y = fmaf(a1.z, b.y, acc4[6].y);
        acc4[6].z = fmaf(a1.z, b.z, acc4[6].z); acc4[6].w = fmaf(a1.z, b.w, acc4[6].w);
        acc4[7].x = fmaf(a1.w, b.x, acc4[7].x); acc4[7].y = fmaf(a1.w, b.y, acc4[7].y);
        acc4[7].z = fmaf(a1.w, b.z, acc4[7].z); acc4[7].w = fmaf(a1.w, b.w, acc4[7].w);
    }
    __syncthreads();
    float4* P4 = (float4*)As;
    #pragma unroll
    for (int r = 0; r < 8; r++) P4[ks * 256 + r * 32 + cg] = acc4[r];
    __syncthreads();
    float4 s = P4[tid];
    #pragma unroll
    for (int sl = 1; sl < 8; sl++) {
        float4 p = P4[sl * 256 + tid];
        s.x += p.x; s.y += p.y; s.z += p.z; s.w += p.w;
    }
    int r = tid >> 5, cc = tid & 31;
    ((float4*)(Y + (size_t)(r0 + r) * 128))[cc] = s;
}

// ---------------- gate: 192 blocks x 256, 8-row tiles, K split in halves ------
__global__ void __launch_bounds__(256) k_gate(const float* __restrict__ lig,
                                              const float* __restrict__ poc,
                                              const float* __restrict__ aggl,
                                              const float* __restrict__ aggp,
                                              const float* __restrict__ Wgl,
                                              const float* __restrict__ bgl,
                                              const float* __restrict__ Wgp,
                                              const float* __restrict__ bgp,
                                              float* __restrict__ lige,
                                              float* __restrict__ poce) {
    __shared__ __align__(16) float xs[1024];
    __shared__ __align__(16) float as_[1024];
    __shared__ float red[1024];
    int tid = threadIdx.x, vb = blockIdx.x;
    const float* X; const float* A; const float* W; const float* B;
    float* Y; int r0;
    if (vb < 64) { X = lig; A = aggl; W = Wgl; B = bgl; Y = lige; r0 = vb * 8; }
    else { X = poc; A = aggp; W = Wgp; B = bgp; Y = poce; r0 = (vb - 64) * 8; }
    ((float4*)xs)[tid] = ((const float4*)(X + (size_t)r0 * 128))[tid];
    ((float4*)as_)[tid] = ((const float4*)(A + (size_t)r0 * 128))[tid];
    __syncthreads();
    int c = tid & 127, part = tid >> 7;
    const ulonglong2* S2 = (const ulonglong2*)(part ? as_ : xs);
    const ulonglong2* w2 = (const ulonglong2*)(W + (size_t)c * 256 + part * 128);
    unsigned long long acc2[8];
    #pragma unroll
    for (int r = 0; r < 8; r++) acc2[r] = 0ull;
    #pragma unroll 8
    for (int kb = 0; kb < 32; kb++) {
        ulonglong2 w = w2[kb];
        #pragma unroll
        for (int r = 0; r < 8; r++) {
            ulonglong2 x = S2[r * 32 + kb];
            acc2[r] = fma2(x.x, w.x, acc2[r]);
            acc2[r] = fma2(x.y, w.y, acc2[r]);
        }
    }
    if (part) {
        #pragma unroll
        for (int r = 0; r < 8; r++) red[c * 8 + r] = hsum2(acc2[r]);
    }
    __syncthreads();
    if (!part) {
        float bv = B[c];
        #pragma unroll
        for (int r = 0; r < 8; r++) {
            float t = hsum2(acc2[r]) + red[c * 8 + r] + bv;
            float g = 1.f / (1.f + __expf(-t));
            float xv = xs[r * 128 + c], av = as_[r * 128 + c];
            Y[(size_t)(r0 + r) * 128 + c] = g * xv + (1.f - g) * av;
        }
    }
}

// ---------------- qkv: 576 blocks x 128, 8-row tiles ---------------------------
__global__ void __launch_bounds__(128) k_qkv(const float* __restrict__ lige,
                                             const float* __restrict__ poce,
                                             const float* __restrict__ W,
                                             const float* __restrict__ B,
                                             float* __restrict__ qkvl,
                                             float* __restrict__ qkvp) {
    __shared__ __align__(16) float Xs[1024];
    int tid = threadIdx.x, vb = blockIdx.x;
    int p = vb / 192, tile = vb % 192;
    const float* X; float* Y; int r0;
    if (tile < 64) { X = lige; Y = qkvl; r0 = tile * 8; }
    else           { X = poce; Y = qkvp; r0 = (tile - 64) * 8; }
    ((float4*)Xs)[tid] = ((const float4*)(X + (size_t)r0 * 128))[tid];
    ((float4*)Xs)[tid + 128] = ((const float4*)(X + (size_t)r0 * 128))[tid + 128];
    __syncthreads();
    const ulonglong2* X2 = (const ulonglong2*)Xs;
    int c = p * 128 + tid;
    const ulonglong2* w2 = (const ulonglong2*)(W + (size_t)c * 128);
    unsigned long long acc2[8] = {0ull, 0ull, 0ull, 0ull, 0ull, 0ull, 0ull, 0ull};
    #pragma unroll 4
    for (int kb = 0; kb < 32; kb++) {
        ulonglong2 w = w2[kb];
        #pragma unroll
        for (int r = 0; r < 8; r++) {
            ulonglong2 x = X2[r * 32 + kb];
            acc2[r] = fma2(x.x, w.x, acc2[r]);
            acc2[r] = fma2(x.y, w.y, acc2[r]);
        }
    }
    float bv = B[c];
    #pragma unroll
    for (int r = 0; r < 8; r++)
        Y[(size_t)(r0 + r) * 384 + c] = hsum2(acc2[r]) + bv;
}

// ---------------- flash attention: 2 queries/warp, f32x2 AV --------------------
// grid(96, 8), block 256 = 8 warps x 2 queries = 16 queries/block.
__global__ void __launch_bounds__(256) k_flash2(const float* __restrict__ qkvl,
                                                const float* __restrict__ qkvp,
                                                float* __restrict__ attl,
                                                float* __restrict__ attp) {
    __shared__ __align__(16) float4 Ks[128 * 5];
    __shared__ __align__(16) float4 Vs[128 * 5];
    int bx = blockIdx.x, h = blockIdx.y;
    int tid = threadIdx.x, w = tid >> 5, lane = tid & 31;
    const float* Qb; const float* KVb; float* outp; int nk, iA;
    if (bx < 32) { Qb = qkvl; KVb = qkvp; outp = attl; nk = 1024; iA = bx * 16 + w * 2; }
    else         { Qb = qkvp; KVb = qkvl; outp = attp; nk = 512; iA = (bx - 32) * 16 + w * 2; }

    const float* qpA = Qb + (size_t)iA * 384 + h * 16;
    float4 qA0 = ((const float4*)qpA)[0], qA1 = ((const float4*)qpA)[1];
    float4 qA2 = ((const float4*)qpA)[2], qA3 = ((const float4*)qpA)[3];
    const float* qpB = qpA + 384;
    float4 qB0 = ((const float4*)qpB)[0], qB1 = ((const float4*)qpB)[1];
    float4 qB2 = ((const float4*)qpB)[2], qB3 = ((const float4*)qpB)[3];

    float mA = -3.4e38f, lA = 0.f, mB = -3.4e38f, lB = 0.f;
    unsigned long long accA[8], accB[8];
    #pragma unroll
    for (int q = 0; q < 8; q++) { accA[q] = 0ull; accB[q] = 0ull; }

    int jload = tid >> 1, cl = (tid & 1) * 2;
    const float* kb0 = KVb + (size_t)jload * 384 + 128 + h * 16 + cl * 4;

    for (int jb = 0; jb < nk; jb += 128) {
        __syncthreads();
        const float* src = kb0 + (size_t)jb * 384;
        Ks[jload * 5 + cl]     = *(const float4*)(src);
        Ks[jload * 5 + cl + 1] = *(const float4*)(src + 4);
        Vs[jload * 5 + cl]     = *(const float4*)(src + 128);
        Vs[jload * 5 + cl + 1] = *(const float4*)(src + 132);
        __syncthreads();

        float sA[4], sB[4];
        #pragma unroll
        for (int jj = 0; jj < 4; jj++) {
            const float4* kr = Ks + (jj * 32 + lane) * 5;
            float4 k0 = kr[0], k1 = kr[1], k2 = kr[2], k3 = kr[3];
            float tA = qA0.x * k0.x;
            tA = fmaf(qA0.y, k0.y, tA); tA = fmaf(qA0.z, k0.z, tA); tA = fmaf(qA0.w, k0.w, tA);
            tA = fmaf(qA1.x, k1.x, tA); tA = fmaf(qA1.y, k1.y, tA);
            tA = fmaf(qA1.z, k1.z, tA); tA = fmaf(qA1.w, k1.w, tA);
            tA = fmaf(qA2.x, k2.x, tA); tA = fmaf(qA2.y, k2.y, tA);
            tA = fmaf(qA2.z, k2.z, tA); tA = fmaf(qA2.w, k2.w, tA);
            tA = fmaf(qA3.x, k3.x, tA); tA = fmaf(qA3.y, k3.y, tA);
            tA = fmaf(qA3.z, k3.z, tA); tA = fmaf(qA3.w, k3.w, tA);
            float tB = qB0.x * k0.x;
            tB = fmaf(qB0.y, k0.y, tB); tB = fmaf(qB0.z, k0.z, tB); tB = fmaf(qB0.w, k0.w, tB);
            tB = fmaf(qB1.x, k1.x, tB); tB = fmaf(qB1.y, k1.y, tB);
            tB = fmaf(qB1.z, k1.z, tB); tB = fmaf(qB1.w, k1.w, tB);
            tB = fmaf(qB2.x, k2.x, tB); tB = fmaf(qB2.y, k2.y, tB);
            tB = fmaf(qB2.z, k2.z, tB); tB = fmaf(qB2.w, k2.w, tB);
            tB = fmaf(qB3.x, k3.x, tB); tB = fmaf(qB3.y, k3.y, tB);
            tB = fmaf(qB3.z, k3.z, tB); tB = fmaf(qB3.w, k3.w, tB);
            sA[jj] = tA * 0.25f;
            sB[jj] = tB * 0.25f;
        }
        float txA = fmaxf(fmaxf(sA[0], sA[1]), fmaxf(sA[2], sA[3]));
        float txB = fmaxf(fmaxf(sB[0], sB[1]), fmaxf(sB[2], sB[3]));
        #pragma unroll
        for (int o = 16; o > 0; o >>= 1) {
            txA = fmaxf(txA, __shfl_xor_sync(0xffffffffu, txA, o));
            txB = fmaxf(txB, __shfl_xor_sync(0xffffffffu, txB, o));
        }
        float mnA = fmaxf(mA, txA), cA = __expf(mA - mnA);
        float mnB = fmaxf(mB, txB), cB = __expf(mB - mnB);
        mA = mnA; mB = mnB; lA *= cA; lB *= cB;
        unsigned long long cA2 = pack2(cA, cA), cB2 = pack2(cB, cB);
        #pragma unroll
        for (int q = 0; q < 8; q++) {
            accA[q] = mul2(accA[q], cA2);
            accB[q] = mul2(accB[q], cB2);
        }
        #pragma unroll
        for (int jj = 0; jj < 4; jj++) {
            float pA = __expf(sA[jj] - mA);
            float pB = __expf(sB[jj] - mB);
            lA += pA; lB += pB;
            unsigned long long pA2 = pack2(pA, pA), pB2 = pack2(pB, pB);
            const ulonglong2* vr = (const ulonglong2*)(Vs + (jj * 32 + lane) * 5);
            #pragma unroll
            for (int q = 0; q < 4; q++) {
                ulonglong2 v = vr[q];
                accA[q * 2]     = fma2(pA2, v.x, accA[q * 2]);
                accA[q * 2 + 1] = fma2(pA2, v.y, accA[q * 2 + 1]);
                accB[q * 2]     = fma2(pB2, v.x, accB[q * 2]);
                accB[q * 2 + 1] = fma2(pB2, v.y, accB[q * 2 + 1]);
            }
        }
    }

    #pragma unroll
    for (int o = 16; o > 0; o >>= 1) {
        lA += __shfl_xor_sync(0xffffffffu, lA, o);
        lB += __shfl_xor_sync(0xffffffffu, lB, o);
    }
    #pragma unroll
    for (int q = 0; q < 8; q++) {
        #pragma unroll
        for (int o = 16; o > 0; o >>= 1) {
            accA[q] = add2(accA[q], __shfl_xor_sync(0xffffffffu, accA[q], o));
            accB[q] = add2(accB[q], __shfl_xor_sync(0xffffffffu, accB[q], o));
        }
    }
    if (lane < 16) {
        float x, y;
        unpack2(accA[lane >> 1], x, y);
        float val = (lane & 1) ? y : x;
        outp[(size_t)iA * 128 + h * 16 + lane] = val * (1.f / lA);
    } else {
        int ll = lane - 16;
        float x, y;
        unpack2(accB[ll >> 1], x, y);
        float val = (ll & 1) ? y : x;
        outp[(size_t)(iA + 1) * 128 + h * 16 + ll] = val * (1.f / lB);
    }
}

// ---------------- out-proj + residual + LN: 192 blocks x 128, 8-row tiles -----
__global__ void __launch_bounds__(128) k_outln(const float* __restrict__ attl,
                                               const float* __restrict__ attp,
                                               const float* __restrict__ W,
                                               const float* __restrict__ bias,
                                               const float* __restrict__ lige,
                                               const float* __restrict__ poce,
                                               const float* __restrict__ g_l,
                                               const float* __restrict__ be_l,
                                               const float* __restrict__ g_p,
                                               const float* __restrict__ be_p,
                                               float* __restrict__ out) {
    __shared__ __align__(16) float Xs[1024];
    __shared__ __align__(16) float T[1024];
    __shared__ float mu[8], iv[8];
    int tid = threadIdx.x, vb = blockIdx.x;
    const float* X; const float* R; const float* gg; const float* bb;
    float* O; int r0;
    if (vb < 64) { X = attl; R = lige; gg = g_l; bb = be_l; O = out; r0 = vb * 8; }
    else {
        X = attp; R = poce; gg = g_p; bb = be_p;
        O = out + 512 * 128; r0 = (vb - 64) * 8;
    }
    ((float4*)Xs)[tid] = ((const float4*)(X + (size_t)r0 * 128))[tid];
    ((float4*)Xs)[tid + 128] = ((const float4*)(X + (size_t)r0 * 128))[tid + 128];
    __syncthreads();
    const ulonglong2* X2 = (const ulonglong2*)Xs;
    const ulonglong2* w2 = (const ulonglong2*)(W + (size_t)tid * 128);
    unsigned long long acc2[8] = {0ull, 0ull, 0ull, 0ull, 0ull, 0ull, 0ull, 0ull};
    #pragma unroll 4
    for (int kb = 0; kb < 32; kb++) {
        ulonglong2 w = w2[kb];
        #pragma unroll
        for (int r = 0; r < 8; r++) {
            ulonglong2 x = X2[r * 32 + kb];
            acc2[r] = fma2(x.x, w.x, acc2[r]);
            acc2[r] = fma2(x.y, w.y, acc2[r]);
        }
    }
    float bv = bias[tid];
    #pragma unroll
    for (int r = 0; r < 8; r++)
        T[r * 128 + tid] = hsum2(acc2[r]) + bv + R[(size_t)(r0 + r) * 128 + tid];
    __syncthreads();

    int wrp = tid >> 5, lane = tid & 31;
    #pragma unroll
    for (int rr = 0; rr < 2; rr++) {
        int r = wrp * 2 + rr;
        float t0 = T[r * 128 + lane], t1 = T[r * 128 + lane + 32];
        float t2 = T[r * 128 + lane + 64], t3 = T[r * 128 + lane + 96];
        float s = (t0 + t1) + (t2 + t3);
        #pragma unroll
        for (int o = 16; o > 0; o >>= 1) s += __shfl_xor_sync(0xffffffffu, s, o);
        float mean = s * (1.f / 128.f);
        float d0 = t0 - mean, d1 = t1 - mean, d2 = t2 - mean, d3 = t3 - mean;
        float v = (d0 * d0 + d1 * d1) + (d2 * d2 + d3 * d3);
        #pragma unroll
        for (int o = 16; o > 0; o >>= 1) v += __shfl_xor_sync(0xffffffffu, v, o);
        if (lane == 0) {
            mu[r] = mean;
            iv[r] = rsqrtf(v * (1.f / 128.f) + 1e-5f);
        }
    }
    __syncthreads();
    float gc = gg[tid], bc = bb[tid];
    #pragma unroll
    for (int r = 0; r < 8; r++) {
        float t = T[r * 128 + tid];
        O[(size_t)(r0 + r) * 128 + tid] = (t - mu[r]) * iv[r] * gc + bc;
    }
}

// ---------------- launch ------------------------------------------------------
extern "C" void kernel_launch(void* const* d_in, const int* in_sizes, int n_in,
                              void* d_out, int out_size) {
    const float* lf   = (const float*)d_in[0];
    const float* pf   = (const float*)d_in[1];
    const float* lc   = (const float*)d_in[2];
    const float* pc   = (const float*)d_in[3];
    const float* Wl   = (const float*)d_in[4];
    const float* bl   = (const float*)d_in[5];
    const float* Wp   = (const float*)d_in[6];
    const float* bp   = (const float*)d_in[7];
    const float* Wd1  = (const float*)d_in[8];
    const float* bd1  = (const float*)d_in[9];
    const float* Wd2  = (const float*)d_in[10];
    const float* bd2  = (const float*)d_in[11];
    const float* Wd3  = (const float*)d_in[12];
    const float* bd3  = (const float*)d_in[13];
    const float* Wgl  = (const float*)d_in[14];
    const float* bgl  = (const float*)d_in[15];
    const float* Wgp  = (const float*)d_in[16];
    const float* bgp  = (const float*)d_in[17];
    const float* Wqkv = (const float*)d_in[18];
    const float* bqkv = (const float*)d_in[19];
    const float* Wo   = (const float*)d_in[20];
    const float* bo   = (const float*)d_in[21];
    const float* g_l  = (const float*)d_in[22];
    const float* be_l = (const float*)d_in[23];
    const float* g_p  = (const float*)d_in[24];
    const float* be_p = (const float*)d_in[25];
    float* out = (float*)d_out;

    float* SB = nullptr;
    cudaGetSymbolAddress((void**)&SB, g_scratch);
    float* s_lig  = SB + OFF_LIG;
    float* s_poc  = SB + OFF_POC;
    float* s_m    = SB + OFF_M;
    float* s_mt   = SB + OFF_MT;
    float* s_aggl = SB + OFF_AGGL;
    float* s_aggp = SB + OFF_AGGP;
    float* s_lige = SB + OFF_LIGE;
    float* s_poce = SB + OFF_POCE;
    float* s_qkvl = SB + OFF_QKVL;
    float* s_qkvp = SB + OFF_QKVP;
    float* s_attl = SB + OFF_ATTL;
    float* s_attp = SB + OFF_ATTP;
    float* s_tab  = SB + OFF_TAB;

    k_pre<<<208, 256>>>(Wd1, bd1, Wd2, bd2, Wd3, bd3, s_tab,
                        lf, pf, Wl, bl, Wp, bp, s_lig, s_poc);
    k_pairm<<<128, 256>>>(lc, pc, s_tab, s_m, s_mt);
    k_aggsoft<<<192, 256>>>(s_m, s_mt, s_poc, s_lig, s_aggl, s_aggp);
    k_gate<<<192, 256>>>(s_lig, s_poc, s_aggl, s_aggp, Wgl, bgl, Wgp, bgp,
                         s_lige, s_poce);
    k_qkv<<<576, 128>>>(s_lige, s_poce, Wqkv, bqkv, s_qkvl, s_qkvp);
    k_flash2<<<dim3(96, 8), 256>>>(s_qkvl, s_qkvp, s_attl, s_attp);
    k_outln<<<192, 128>>>(s_attl, s_attp, Wo, bo, s_lige, s_poce,
                          g_l, be_l, g_p, be_p, out);
}

// round 15
// speedup vs baseline: 1.1073x; 1.0311x over previous
#include <cuda_runtime.h>
#include <math.h>

// ---------------- scratch (device globals; no allocation allowed) ----------
#define OFF_LIG     0           // 512*128
#define OFF_POC     65536       // 1024*128
#define OFF_AGGL    196608      // 512*128
#define OFF_AGGP    262144      // 1024*128
#define OFF_LIGE    393216      // 512*128
#define OFF_POCE    458752      // 1024*128
#define OFF_QKVL    589824      // 512*384
#define OFF_QKVP    786432      // 1024*384
#define OFF_ATTL    1179648     // 512*128
#define OFF_ATTP    1245184     // 1024*128
#define OFF_TAB     1376256     // 4096
#define SCRATCH_FLOATS 1380352

__device__ float g_scratch[SCRATCH_FLOATS];

#define TAB_N 4096
#define D_MAX 35.0f

// ---------------- f32x2 helpers ----------------------------------------------
__device__ __forceinline__ unsigned long long fma2(unsigned long long a,
                                                   unsigned long long b,
                                                   unsigned long long c) {
    unsigned long long d;
    asm("fma.rn.f32x2 %0, %1, %2, %3;" : "=l"(d) : "l"(a), "l"(b), "l"(c));
    return d;
}
__device__ __forceinline__ unsigned long long mul2(unsigned long long a,
                                                   unsigned long long b) {
    unsigned long long d;
    asm("mul.rn.f32x2 %0, %1, %2;" : "=l"(d) : "l"(a), "l"(b));
    return d;
}
__device__ __forceinline__ unsigned long long add2(unsigned long long a,
                                                   unsigned long long b) {
    unsigned long long d;
    asm("add.rn.f32x2 %0, %1, %2;" : "=l"(d) : "l"(a), "l"(b));
    return d;
}
__device__ __forceinline__ unsigned long long pack2(float x, float y) {
    unsigned long long r;
    asm("mov.b64 %0, {%1, %2};" : "=l"(r) : "f"(x), "f"(y));
    return r;
}
__device__ __forceinline__ void unpack2(unsigned long long v, float& x, float& y) {
    asm("mov.b64 {%0, %1}, %2;" : "=f"(x), "=f"(y) : "l"(v));
}
__device__ __forceinline__ float hsum2(unsigned long long v) {
    float x, y;
    unpack2(v, x, y);
    return x + y;
}

// ---------------- k_pre: 208 blocks x 256 (2 subtiles) -------------------------
__global__ void __launch_bounds__(256) k_pre(const float* __restrict__ Wd1,
                                             const float* __restrict__ bd1,
                                             const float* __restrict__ Wd2,
                                             const float* __restrict__ bd2,
                                             const float* __restrict__ Wd3,
                                             const float* __restrict__ bd3,
                                             float* __restrict__ tab,
                                             const float* __restrict__ lf,
                                             const float* __restrict__ pf,
                                             const float* __restrict__ Wl,
                                             const float* __restrict__ bl,
                                             const float* __restrict__ Wp,
                                             const float* __restrict__ bp,
                                             float* __restrict__ lig,
                                             float* __restrict__ poc) {
    __shared__ __align__(16) float smem[2 * 2304];
    int tid = threadIdx.x;
    int sub = tid >> 7, st = tid & 127;
    int vb = blockIdx.x * 2 + sub;
    float* sbuf = smem + sub * 2304;
    float* w1s = sbuf + 2048;
    float* b1s = w1s + 32;
    float* b2s = b1s + 32;
    float* wms = b2s + 64;
    float* mcs = wms + 64;

    if (vb < 32) {
        for (int idx = st; idx < 2048; idx += 128) sbuf[idx] = Wd2[idx];
        if (st < 32) { w1s[st] = Wd1[st]; b1s[st] = bd1[st]; }
        if (st >= 32 && st < 96) b2s[st - 32] = bd2[st - 32];
        if (st < 64) {
            float s = 0.f;
            for (int i = 0; i < 128; i++) s += Wd3[i * 64 + st];
            wms[st] = s * (1.f / 128.f);
        }
        if (st == 127) {
            float s = 0.f;
            for (int i = 0; i < 128; i++) s += bd3[i];
            *mcs = s * (1.f / 128.f);
        }
        __syncthreads();
        int idx = vb * 128 + st;
        float d = (float)idx * (D_MAX / (float)(TAB_N - 1));
        float h1[32];
        #pragma unroll
        for (int k = 0; k < 32; k++) h1[k] = fmaxf(fmaf(d, w1s[k], b1s[k]), 0.f);
        float mval = *mcs;
        #pragma unroll 1
        for (int j = 0; j < 64; j++) {
            const float4* wr = (const float4*)(sbuf + j * 32);
            float a0 = 0.f, a1 = 0.f, a2 = 0.f, a3 = 0.f;
            #pragma unroll
            for (int q = 0; q < 8; q++) {
                float4 w = wr[q];
                a0 = fmaf(w.x, h1[4 * q + 0], a0);
                a1 = fmaf(w.y, h1[4 * q + 1], a1);
                a2 = fmaf(w.z, h1[4 * q + 2], a2);
                a3 = fmaf(w.w, h1[4 * q + 3], a3);
            }
            float pre = b2s[j] + ((a0 + a1) + (a2 + a3));
            mval = fmaf(fmaxf(pre, 0.f), wms[j], mval);
        }
        tab[idx] = mval;
    } else {
        int pb = vb - 32;
        const float* X; const float* W; const float* B; float* Y; int r0;
        if (pb < 128) { X = lf; W = Wl; B = bl; Y = lig; r0 = pb * 4; }
        else          { X = pf; W = Wp; B = bp; Y = poc; r0 = (pb - 128) * 4; }
        ((float4*)sbuf)[st] = ((const float4*)(X + (size_t)r0 * 128))[st];
        __syncthreads();
        const ulonglong2* X2 = (const ulonglong2*)sbuf;
        const ulonglong2* w2 = (const ulonglong2*)(W + (size_t)st * 128);
        unsigned long long acc2[4] = {0ull, 0ull, 0ull, 0ull};
        #pragma unroll 8
        for (int kb = 0; kb < 32; kb++) {
            ulonglong2 w = w2[kb];
            #pragma unroll
            for (int r = 0; r < 4; r++) {
                ulonglong2 x = X2[r * 32 + kb];
                acc2[r] = fma2(x.x, w.x, acc2[r]);
                acc2[r] = fma2(x.y, w.y, acc2[r]);
            }
        }
        float bv = B[st];
        #pragma unroll
        for (int r = 0; r < 4; r++)
            Y[(size_t)(r0 + r) * 128 + st] = hsum2(acc2[r]) + bv;
    }
}

// ---------------- aggsoft: inline pair-m + softmax + register-blocked GEMM ----
// grid 192, block 256, dynamic smem: tabs[4096] | cs[3072] | As[8192].
__global__ void __launch_bounds__(256) k_aggsoft(const float* __restrict__ lc,
                                                 const float* __restrict__ pc,
                                                 const float* __restrict__ tab,
                                                 const float* __restrict__ poc,
                                                 const float* __restrict__ lig,
                                                 float* __restrict__ aggl,
                                                 float* __restrict__ aggp) {
    extern __shared__ __align__(16) float dsm[];
    float* tabs = dsm;                // 4096
    float* cs   = dsm + TAB_N;        // 3072 (other-side coords)
    float* As   = dsm + TAB_N + 3072; // 8192
    int tid = threadIdx.x, bx = blockIdx.x;
    const float* B; float* Y; const float* own; const float* other; int r0, K;
    if (bx < 64) { B = poc; Y = aggl; own = lc; other = pc; r0 = bx * 8;        K = 1024; }
    else         { B = lig; Y = aggp; own = pc; other = lc; r0 = (bx - 64) * 8; K = 512;  }

    for (int idx = tid; idx < TAB_N; idx += 256) tabs[idx] = tab[idx];
    for (int idx = tid; idx < 3 * K; idx += 256) cs[idx] = other[idx];
    __syncthreads();

    // ---- softmax phase: warp per row, m recomputed inline (table lerp) ----
    int w = tid >> 5, lane = tid & 31;
    float ox = own[(r0 + w) * 3 + 0];
    float oy = own[(r0 + w) * 3 + 1];
    float oz = own[(r0 + w) * 3 + 2];
    const float invh = (float)(TAB_N - 1) / D_MAX;
    if (K == 1024) {
        float mv[32];
        float mx = -3.4e38f;
        #pragma unroll
        for (int t = 0; t < 32; t++) {
            int j = t * 32 + lane;
            float dx = ox - cs[j * 3 + 0];
            float dy = oy - cs[j * 3 + 1];
            float dz = oz - cs[j * 3 + 2];
            float d = sqrtf(fmaf(dx, dx, fmaf(dy, dy, dz * dz)));
            float tt = d * invh;
            int t0 = min((int)tt, TAB_N - 2);
            float f = tt - (float)t0;
            float v0 = tabs[t0], v1 = tabs[t0 + 1];
            float v = -fmaf(f, v1 - v0, v0);
            mv[t] = v;
            mx = fmaxf(mx, v);
        }
        #pragma unroll
        for (int o = 16; o > 0; o >>= 1)
            mx = fmaxf(mx, __shfl_xor_sync(0xffffffffu, mx, o));
        float sum = 0.f;
        #pragma unroll
        for (int t = 0; t < 32; t++) {
            float e = __expf(mv[t] - mx);
            mv[t] = e;
            sum += e;
        }
        #pragma unroll
        for (int o = 16; o > 0; o >>= 1)
            sum += __shfl_xor_sync(0xffffffffu, sum, o);
        float inv = 1.f / sum;
        #pragma unroll
        for (int t = 0; t < 32; t++) As[(t * 32 + lane) * 8 + w] = mv[t] * inv;
    } else {
        float mv[16];
        float mx = -3.4e38f;
        #pragma unroll
        for (int t = 0; t < 16; t++) {
            int j = t * 32 + lane;
            float dx = ox - cs[j * 3 + 0];
            float dy = oy - cs[j * 3 + 1];
            float dz = oz - cs[j * 3 + 2];
            float d = sqrtf(fmaf(dx, dx, fmaf(dy, dy, dz * dz)));
            float tt = d * invh;
            int t0 = min((int)tt, TAB_N - 2);
            float f = tt - (float)t0;
            float v0 = tabs[t0], v1 = tabs[t0 + 1];
            float v = -fmaf(f, v1 - v0, v0);
            mv[t] = v;
            mx = fmaxf(mx, v);
        }
        #pragma unroll
        for (int o = 16; o > 0; o >>= 1)
            mx = fmaxf(mx, __shfl_xor_sync(0xffffffffu, mx, o));
        float sum = 0.f;
        #pragma unroll
        for (int t = 0; t < 16; t++) {
            float e = __expf(mv[t] - mx);
            mv[t] = e;
            sum += e;
        }
        #pragma unroll
        for (int o = 16; o > 0; o >>= 1)
            sum += __shfl_xor_sync(0xffffffffu, sum, o);
        float inv = 1.f / sum;
        #pragma unroll
        for (int t = 0; t < 16; t++) As[(t * 32 + lane) * 8 + w] = mv[t] * inv;
    }
    __syncthreads();

    // ---- GEMM phase: cg = 4 cols, ks = K/8 slice ----
    int cg = tid & 31, ks = tid >> 5;
    int steps = K >> 3;
    int kstart = ks * steps;
    float4 acc4[8];
    #pragma unroll
    for (int r = 0; r < 8; r++) acc4[r] = make_float4(0.f, 0.f, 0.f, 0.f);
    const float4* As4 = (const float4*)As;
    const float4* B4 = (const float4*)B;
    #pragma unroll 2
    for (int kk = 0; kk < steps; kk++) {
        int k = kstart + kk;
        float4 a0 = As4[k * 2 + 0];
        float4 a1 = As4[k * 2 + 1];
        float4 b = B4[(size_t)k * 32 + cg];
        acc4[0].x = fmaf(a0.x, b.x, acc4[0].x); acc4[0].y = fmaf(a0.x, b.y, acc4[0].y);
        acc4[0].z = fmaf(a0.x, b.z, acc4[0].z); acc4[0].w = fmaf(a0.x, b.w, acc4[0].w);
        acc4[1].x = fmaf(a0.y, b.x, acc4[1].x); acc4[1].y = fmaf(a0.y, b.y, acc4[1].y);
        acc4[1].z = fmaf(a0.y, b.z, acc4[1].z); acc4[1].w = fmaf(a0.y, b.w, acc4[1].w);
        acc4[2].x = fmaf(a0.z, b.x, acc4[2].x); acc4[2].y = fmaf(a0.z, b.y, acc4[2].y);
        acc4[2].z = fmaf(a0.z, b.z, acc4[2].z); acc4[2].w = fmaf(a0.z, b.w, acc4[2].w);
        acc4[3].x = fmaf(a0.w, b.x, acc4[3].x); acc4[3].y = fmaf(a0.w, b.y, acc4[3].y);
        acc4[3].z = fmaf(a0.w, b.z, acc4[3].z); acc4[3].w = fmaf(a0.w, b.w, acc4[3].w);
        acc4[4].x = fmaf(a1.x, b.x, acc4[4].x); acc4[4].y = fmaf(a1.x, b.y, acc4[4].y);
        acc4[4].z = fmaf(a1.x, b.z, acc4[4].z); acc4[4].w = fmaf(a1.x, b.w, acc4[4].w);
        acc4[5].x = fmaf(a1.y, b.x, acc4[5].x); acc4[5].y = fmaf(a1.y, b.y, acc4[5].y);
        acc4[5].z = fmaf(a1.y, b.z, acc4[5].z); acc4[5].w = fmaf(a1.y, b.w, acc4[5].w);
        acc4[6].x = fmaf(a1.z, b.x, acc4[6].x); acc4[6].y = fmaf(a1.z, b.y, acc4[6].y);
        acc4[6].z = fmaf(a1.z, b.z, acc4[6].z); acc4[6].w = fmaf(a1.z, b.w, acc4[6].w);
        acc4[7].x = fmaf(a1.w, b.x, acc4[7].x); acc4[7].y = fmaf(a1.w, b.y, acc4[7].y);
        acc4[7].z = fmaf(a1.w, b.z, acc4[7].z); acc4[7].w = fmaf(a1.w, b.w, acc4[7].w);
    }
    __syncthreads();
    float4* P4 = (float4*)As;
    #pragma unroll
    for (int r = 0; r < 8; r++) P4[ks * 256 + r * 32 + cg] = acc4[r];
    __syncthreads();
    float4 s = P4[tid];
    #pragma unroll
    for (int sl = 1; sl < 8; sl++) {
        float4 p = P4[sl * 256 + tid];
        s.x += p.x; s.y += p.y; s.z += p.z; s.w += p.w;
    }
    int r = tid >> 5, cc = tid & 31;
    ((float4*)(Y + (size_t)(r0 + r) * 128))[cc] = s;
}

// ---------------- gate: 192 blocks x 256, 8-row tiles, K split in halves ------
__global__ void __launch_bounds__(256) k_gate(const float* __restrict__ lig,
                                              const float* __restrict__ poc,
                                              const float* __restrict__ aggl,
                                              const float* __restrict__ aggp,
                                              const float* __restrict__ Wgl,
                                              const float* __restrict__ bgl,
                                              const float* __restrict__ Wgp,
                                              const float* __restrict__ bgp,
                                              float* __restrict__ lige,
                                              float* __restrict__ poce) {
    __shared__ __align__(16) float xs[1024];
    __shared__ __align__(16) float as_[1024];
    __shared__ float red[1024];
    int tid = threadIdx.x, vb = blockIdx.x;
    const float* X; const float* A; const float* W; const float* B;
    float* Y; int r0;
    if (vb < 64) { X = lig; A = aggl; W = Wgl; B = bgl; Y = lige; r0 = vb * 8; }
    else { X = poc; A = aggp; W = Wgp; B = bgp; Y = poce; r0 = (vb - 64) * 8; }
    ((float4*)xs)[tid] = ((const float4*)(X + (size_t)r0 * 128))[tid];
    ((float4*)as_)[tid] = ((const float4*)(A + (size_t)r0 * 128))[tid];
    __syncthreads();
    int c = tid & 127, part = tid >> 7;
    const ulonglong2* S2 = (const ulonglong2*)(part ? as_ : xs);
    const ulonglong2* w2 = (const ulonglong2*)(W + (size_t)c * 256 + part * 128);
    unsigned long long acc2[8];
    #pragma unroll
    for (int r = 0; r < 8; r++) acc2[r] = 0ull;
    #pragma unroll 8
    for (int kb = 0; kb < 32; kb++) {
        ulonglong2 w = w2[kb];
        #pragma unroll
        for (int r = 0; r < 8; r++) {
            ulonglong2 x = S2[r * 32 + kb];
            acc2[r] = fma2(x.x, w.x, acc2[r]);
            acc2[r] = fma2(x.y, w.y, acc2[r]);
        }
    }
    if (part) {
        #pragma unroll
        for (int r = 0; r < 8; r++) red[c * 8 + r] = hsum2(acc2[r]);
    }
    __syncthreads();
    if (!part) {
        float bv = B[c];
        #pragma unroll
        for (int r = 0; r < 8; r++) {
            float t = hsum2(acc2[r]) + red[c * 8 + r] + bv;
            float g = 1.f / (1.f + __expf(-t));
            float xv = xs[r * 128 + c], av = as_[r * 128 + c];
            Y[(size_t)(r0 + r) * 128 + c] = g * xv + (1.f - g) * av;
        }
    }
}

// ---------------- qkv: 576 blocks x 128, 8-row tiles ---------------------------
__global__ void __launch_bounds__(128) k_qkv(const float* __restrict__ lige,
                                             const float* __restrict__ poce,
                                             const float* __restrict__ W,
                                             const float* __restrict__ B,
                                             float* __restrict__ qkvl,
                                             float* __restrict__ qkvp) {
    __shared__ __align__(16) float Xs[1024];
    int tid = threadIdx.x, vb = blockIdx.x;
    int p = vb / 192, tile = vb % 192;
    const float* X; float* Y; int r0;
    if (tile < 64) { X = lige; Y = qkvl; r0 = tile * 8; }
    else           { X = poce; Y = qkvp; r0 = (tile - 64) * 8; }
    ((float4*)Xs)[tid] = ((const float4*)(X + (size_t)r0 * 128))[tid];
    ((float4*)Xs)[tid + 128] = ((const float4*)(X + (size_t)r0 * 128))[tid + 128];
    __syncthreads();
    const ulonglong2* X2 = (const ulonglong2*)Xs;
    int c = p * 128 + tid;
    const ulonglong2* w2 = (const ulonglong2*)(W + (size_t)c * 128);
    unsigned long long acc2[8] = {0ull, 0ull, 0ull, 0ull, 0ull, 0ull, 0ull, 0ull};
    #pragma unroll 4
    for (int kb = 0; kb < 32; kb++) {
        ulonglong2 w = w2[kb];
        #pragma unroll
        for (int r = 0; r < 8; r++) {
            ulonglong2 x = X2[r * 32 + kb];
            acc2[r] = fma2(x.x, w.x, acc2[r]);
            acc2[r] = fma2(x.y, w.y, acc2[r]);
        }
    }
    float bv = B[c];
    #pragma unroll
    for (int r = 0; r < 8; r++)
        Y[(size_t)(r0 + r) * 384 + c] = hsum2(acc2[r]) + bv;
}

// ---------------- flash attention: 2 queries/warp, f32x2 AV --------------------
// grid(96, 8), block 256 = 8 warps x 2 queries = 16 queries/block.
__global__ void __launch_bounds__(256) k_flash2(const float* __restrict__ qkvl,
                                                const float* __restrict__ qkvp,
                                                float* __restrict__ attl,
                                                float* __restrict__ attp) {
    __shared__ __align__(16) float4 Ks[128 * 5];
    __shared__ __align__(16) float4 Vs[128 * 5];
    int bx = blockIdx.x, h = blockIdx.y;
    int tid = threadIdx.x, w = tid >> 5, lane = tid & 31;
    const float* Qb; const float* KVb; float* outp; int nk, iA;
    if (bx < 32) { Qb = qkvl; KVb = qkvp; outp = attl; nk = 1024; iA = bx * 16 + w * 2; }
    else         { Qb = qkvp; KVb = qkvl; outp = attp; nk = 512; iA = (bx - 32) * 16 + w * 2; }

    const float* qpA = Qb + (size_t)iA * 384 + h * 16;
    float4 qA0 = ((const float4*)qpA)[0], qA1 = ((const float4*)qpA)[1];
    float4 qA2 = ((const float4*)qpA)[2], qA3 = ((const float4*)qpA)[3];
    const float* qpB = qpA + 384;
    float4 qB0 = ((const float4*)qpB)[0], qB1 = ((const float4*)qpB)[1];
    float4 qB2 = ((const float4*)qpB)[2], qB3 = ((const float4*)qpB)[3];

    float mA = -3.4e38f, lA = 0.f, mB = -3.4e38f, lB = 0.f;
    unsigned long long accA[8], accB[8];
    #pragma unroll
    for (int q = 0; q < 8; q++) { accA[q] = 0ull; accB[q] = 0ull; }

    int jload = tid >> 1, cl = (tid & 1) * 2;
    const float* kb0 = KVb + (size_t)jload * 384 + 128 + h * 16 + cl * 4;

    for (int jb = 0; jb < nk; jb += 128) {
        __syncthreads();
        const float* src = kb0 + (size_t)jb * 384;
        Ks[jload * 5 + cl]     = *(const float4*)(src);
        Ks[jload * 5 + cl + 1] = *(const float4*)(src + 4);
        Vs[jload * 5 + cl]     = *(const float4*)(src + 128);
        Vs[jload * 5 + cl + 1] = *(const float4*)(src + 132);
        __syncthreads();

        float sA[4], sB[4];
        #pragma unroll
        for (int jj = 0; jj < 4; jj++) {
            const float4* kr = Ks + (jj * 32 + lane) * 5;
            float4 k0 = kr[0], k1 = kr[1], k2 = kr[2], k3 = kr[3];
            float tA = qA0.x * k0.x;
            tA = fmaf(qA0.y, k0.y, tA); tA = fmaf(qA0.z, k0.z, tA); tA = fmaf(qA0.w, k0.w, tA);
            tA = fmaf(qA1.x, k1.x, tA); tA = fmaf(qA1.y, k1.y, tA);
            tA = fmaf(qA1.z, k1.z, tA); tA = fmaf(qA1.w, k1.w, tA);
            tA = fmaf(qA2.x, k2.x, tA); tA = fmaf(qA2.y, k2.y, tA);
            tA = fmaf(qA2.z, k2.z, tA); tA = fmaf(qA2.w, k2.w, tA);
            tA = fmaf(qA3.x, k3.x, tA); tA = fmaf(qA3.y, k3.y, tA);
            tA = fmaf(qA3.z, k3.z, tA); tA = fmaf(qA3.w, k3.w, tA);
            float tB = qB0.x * k0.x;
            tB = fmaf(qB0.y, k0.y, tB); tB = fmaf(qB0.z, k0.z, tB); tB = fmaf(qB0.w, k0.w, tB);
            tB = fmaf(qB1.x, k1.x, tB); tB = fmaf(qB1.y, k1.y, tB);
            tB = fmaf(qB1.z, k1.z, tB); tB = fmaf(qB1.w, k1.w, tB);
            tB = fmaf(qB2.x, k2.x, tB); tB = fmaf(qB2.y, k2.y, tB);
            tB = fmaf(qB2.z, k2.z, tB); tB = fmaf(qB2.w, k2.w, tB);
            tB = fmaf(qB3.x, k3.x, tB); tB = fmaf(qB3.y, k3.y, tB);
            tB = fmaf(qB3.z, k3.z, tB); tB = fmaf(qB3.w, k3.w, tB);
            sA[jj] = tA * 0.25f;
            sB[jj] = tB * 0.25f;
        }
        float txA = fmaxf(fmaxf(sA[0], sA[1]), fmaxf(sA[2], sA[3]));
        float txB = fmaxf(fmaxf(sB[0], sB[1]), fmaxf(sB[2], sB[3]));
        #pragma unroll
        for (int o = 16; o > 0; o >>= 1) {
            txA = fmaxf(txA, __shfl_xor_sync(0xffffffffu, txA, o));
            txB = fmaxf(txB, __shfl_xor_sync(0xffffffffu, txB, o));
        }
        float mnA = fmaxf(mA, txA), cA = __expf(mA - mnA);
        float mnB = fmaxf(mB, txB), cB = __expf(mB - mnB);
        mA = mnA; mB = mnB; lA *= cA; lB *= cB;
        unsigned long long cA2 = pack2(cA, cA), cB2 = pack2(cB, cB);
        #pragma unroll
        for (int q = 0; q < 8; q++) {
            accA[q] = mul2(accA[q], cA2);
            accB[q] = mul2(accB[q], cB2);
        }
        #pragma unroll
        for (int jj = 0; jj < 4; jj++) {
            float pA = __expf(sA[jj] - mA);
            float pB = __expf(sB[jj] - mB);
            lA += pA; lB += pB;
            unsigned long long pA2 = pack2(pA, pA), pB2 = pack2(pB, pB);
            const ulonglong2* vr = (const ulonglong2*)(Vs + (jj * 32 + lane) * 5);
            #pragma unroll
            for (int q = 0; q < 4; q++) {
                ulonglong2 v = vr[q];
                accA[q * 2]     = fma2(pA2, v.x, accA[q * 2]);
                accA[q * 2 + 1] = fma2(pA2, v.y, accA[q * 2 + 1]);
                accB[q * 2]     = fma2(pB2, v.x, accB[q * 2]);
                accB[q * 2 + 1] = fma2(pB2, v.y, accB[q * 2 + 1]);
            }
        }
    }

    #pragma unroll
    for (int o = 16; o > 0; o >>= 1) {
        lA += __shfl_xor_sync(0xffffffffu, lA, o);
        lB += __shfl_xor_sync(0xffffffffu, lB, o);
    }
    #pragma unroll
    for (int q = 0; q < 8; q++) {
        #pragma unroll
        for (int o = 16; o > 0; o >>= 1) {
            accA[q] = add2(accA[q], __shfl_xor_sync(0xffffffffu, accA[q], o));
            accB[q] = add2(accB[q], __shfl_xor_sync(0xffffffffu, accB[q], o));
        }
    }
    if (lane < 16) {
        float x, y;
        unpack2(accA[lane >> 1], x, y);
        float val = (lane & 1) ? y : x;
        outp[(size_t)iA * 128 + h * 16 + lane] = val * (1.f / lA);
    } else {
        int ll = lane - 16;
        float x, y;
        unpack2(accB[ll >> 1], x, y);
        float val = (ll & 1) ? y : x;
        outp[(size_t)(iA + 1) * 128 + h * 16 + ll] = val * (1.f / lB);
    }
}

// ---------------- out-proj + residual + LN: 192 blocks x 128, 8-row tiles -----
__global__ void __launch_bounds__(128) k_outln(const float* __restrict__ attl,
                                               const float* __restrict__ attp,
                                               const float* __restrict__ W,
                                               const float* __restrict__ bias,
                                               const float* __restrict__ lige,
                                               const float* __restrict__ poce,
                                               const float* __restrict__ g_l,
                                               const float* __restrict__ be_l,
                                               const float* __restrict__ g_p,
                                               const float* __restrict__ be_p,
                                               float* __restrict__ out) {
    __shared__ __align__(16) float Xs[1024];
    __shared__ __align__(16) float T[1024];
    __shared__ float mu[8], iv[8];
    int tid = threadIdx.x, vb = blockIdx.x;
    const float* X; const float* R; const float* gg; const float* bb;
    float* O; int r0;
    if (vb < 64) { X = attl; R = lige; gg = g_l; bb = be_l; O = out; r0 = vb * 8; }
    else {
        X = attp; R = poce; gg = g_p; bb = be_p;
        O = out + 512 * 128; r0 = (vb - 64) * 8;
    }
    ((float4*)Xs)[tid] = ((const float4*)(X + (size_t)r0 * 128))[tid];
    ((float4*)Xs)[tid + 128] = ((const float4*)(X + (size_t)r0 * 128))[tid + 128];
    __syncthreads();
    const ulonglong2* X2 = (const ulonglong2*)Xs;
    const ulonglong2* w2 = (const ulonglong2*)(W + (size_t)tid * 128);
    unsigned long long acc2[8] = {0ull, 0ull, 0ull, 0ull, 0ull, 0ull, 0ull, 0ull};
    #pragma unroll 4
    for (int kb = 0; kb < 32; kb++) {
        ulonglong2 w = w2[kb];
        #pragma unroll
        for (int r = 0; r < 8; r++) {
            ulonglong2 x = X2[r * 32 + kb];
            acc2[r] = fma2(x.x, w.x, acc2[r]);
            acc2[r] = fma2(x.y, w.y, acc2[r]);
        }
    }
    float bv = bias[tid];
    #pragma unroll
    for (int r = 0; r < 8; r++)
        T[r * 128 + tid] = hsum2(acc2[r]) + bv + R[(size_t)(r0 + r) * 128 + tid];
    __syncthreads();

    int wrp = tid >> 5, lane = tid & 31;
    #pragma unroll
    for (int rr = 0; rr < 2; rr++) {
        int r = wrp * 2 + rr;
        float t0 = T[r * 128 + lane], t1 = T[r * 128 + lane + 32];
        float t2 = T[r * 128 + lane + 64], t3 = T[r * 128 + lane + 96];
        float s = (t0 + t1) + (t2 + t3);
        #pragma unroll
        for (int o = 16; o > 0; o >>= 1) s += __shfl_xor_sync(0xffffffffu, s, o);
        float mean = s * (1.f / 128.f);
        float d0 = t0 - mean, d1 = t1 - mean, d2 = t2 - mean, d3 = t3 - mean;
        float v = (d0 * d0 + d1 * d1) + (d2 * d2 + d3 * d3);
        #pragma unroll
        for (int o = 16; o > 0; o >>= 1) v += __shfl_xor_sync(0xffffffffu, v, o);
        if (lane == 0) {
            mu[r] = mean;
            iv[r] = rsqrtf(v * (1.f / 128.f) + 1e-5f);
        }
    }
    __syncthreads();
    float gc = gg[tid], bc = bb[tid];
    #pragma unroll
    for (int r = 0; r < 8; r++) {
        float t = T[r * 128 + tid];
        O[(size_t)(r0 + r) * 128 + tid] = (t - mu[r]) * iv[r] * gc + bc;
    }
}

// ---------------- launch ------------------------------------------------------
extern "C" void kernel_launch(void* const* d_in, const int* in_sizes, int n_in,
                              void* d_out, int out_size) {
    const float* lf   = (const float*)d_in[0];
    const float* pf   = (const float*)d_in[1];
    const float* lc   = (const float*)d_in[2];
    const float* pc   = (const float*)d_in[3];
    const float* Wl   = (const float*)d_in[4];
    const float* bl   = (const float*)d_in[5];
    const float* Wp   = (const float*)d_in[6];
    const float* bp   = (const float*)d_in[7];
    const float* Wd1  = (const float*)d_in[8];
    const float* bd1  = (const float*)d_in[9];
    const float* Wd2  = (const float*)d_in[10];
    const float* bd2  = (const float*)d_in[11];
    const float* Wd3  = (const float*)d_in[12];
    const float* bd3  = (const float*)d_in[13];
    const float* Wgl  = (const float*)d_in[14];
    const float* bgl  = (const float*)d_in[15];
    const float* Wgp  = (const float*)d_in[16];
    const float* bgp  = (const float*)d_in[17];
    const float* Wqkv = (const float*)d_in[18];
    const float* bqkv = (const float*)d_in[19];
    const float* Wo   = (const float*)d_in[20];
    const float* bo   = (const float*)d_in[21];
    const float* g_l  = (const float*)d_in[22];
    const float* be_l = (const float*)d_in[23];
    const float* g_p  = (const float*)d_in[24];
    const float* be_p = (const float*)d_in[25];
    float* out = (float*)d_out;

    float* SB = nullptr;
    cudaGetSymbolAddress((void**)&SB, g_scratch);
    float* s_lig  = SB + OFF_LIG;
    float* s_poc  = SB + OFF_POC;
    float* s_aggl = SB + OFF_AGGL;
    float* s_aggp = SB + OFF_AGGP;
    float* s_lige = SB + OFF_LIGE;
    float* s_poce = SB + OFF_POCE;
    float* s_qkvl = SB + OFF_QKVL;
    float* s_qkvp = SB + OFF_QKVP;
    float* s_attl = SB + OFF_ATTL;
    float* s_attp = SB + OFF_ATTP;
    float* s_tab  = SB + OFF_TAB;

    static bool s_attr_set = false;
    if (!s_attr_set) {
        cudaFuncSetAttribute(k_aggsoft,
                             cudaFuncAttributeMaxDynamicSharedMemorySize,
                             (TAB_N + 3072 + 8192) * 4);
        s_attr_set = true;
    }

    k_pre<<<208, 256>>>(Wd1, bd1, Wd2, bd2, Wd3, bd3, s_tab,
                        lf, pf, Wl, bl, Wp, bp, s_lig, s_poc);
    k_aggsoft<<<192, 256, (TAB_N + 3072 + 8192) * 4>>>(lc, pc, s_tab, s_poc,
                                                       s_lig, s_aggl, s_aggp);
    k_gate<<<192, 256>>>(s_lig, s_poc, s_aggl, s_aggp, Wgl, bgl, Wgp, bgp,
                         s_lige, s_poce);
    k_qkv<<<576, 128>>>(s_lige, s_poce, Wqkv, bqkv, s_qkvl, s_qkvp);
    k_flash2<<<dim3(96, 8), 256>>>(s_qkvl, s_qkvp, s_attl, s_attp);
    k_outln<<<192, 128>>>(s_attl, s_attp, Wo, bo, s_lige, s_poce,
                          g_l, be_l, g_p, be_p, out);
}

// round 16
// speedup vs baseline: 1.1677x; 1.0545x over previous
#include <cuda_runtime.h>
#include <math.h>

// ---------------- scratch (device globals; no allocation allowed) ----------
#define OFF_LIG     0           // 512*128
#define OFF_POC     65536       // 1024*128
#define OFF_AGGL    196608      // 512*128
#define OFF_AGGP    262144      // 1024*128
#define OFF_LIGE    393216      // 512*128
#define OFF_POCE    458752      // 1024*128
#define OFF_QKVL    589824      // 512*384
#define OFF_QKVP    786432      // 1024*384
#define OFF_ATTL    1179648     // 512*128
#define OFF_ATTP    1245184     // 1024*128
#define OFF_TAB     1376256     // 4096
#define SCRATCH_FLOATS 1380352

__device__ float g_scratch[SCRATCH_FLOATS];

#define TAB_N 4096
#define D_MAX 35.0f

// ---------------- f32x2 helpers ----------------------------------------------
__device__ __forceinline__ unsigned long long fma2(unsigned long long a,
                                                   unsigned long long b,
                                                   unsigned long long c) {
    unsigned long long d;
    asm("fma.rn.f32x2 %0, %1, %2, %3;" : "=l"(d) : "l"(a), "l"(b), "l"(c));
    return d;
}
__device__ __forceinline__ unsigned long long mul2(unsigned long long a,
                                                   unsigned long long b) {
    unsigned long long d;
    asm("mul.rn.f32x2 %0, %1, %2;" : "=l"(d) : "l"(a), "l"(b));
    return d;
}
__device__ __forceinline__ unsigned long long add2(unsigned long long a,
                                                   unsigned long long b) {
    unsigned long long d;
    asm("add.rn.f32x2 %0, %1, %2;" : "=l"(d) : "l"(a), "l"(b));
    return d;
}
__device__ __forceinline__ unsigned long long pack2(float x, float y) {
    unsigned long long r;
    asm("mov.b64 %0, {%1, %2};" : "=l"(r) : "f"(x), "f"(y));
    return r;
}
__device__ __forceinline__ void unpack2(unsigned long long v, float& x, float& y) {
    asm("mov.b64 {%0, %1}, %2;" : "=f"(x), "=f"(y) : "l"(v));
}
__device__ __forceinline__ float hsum2(unsigned long long v) {
    float x, y;
    unpack2(v, x, y);
    return x + y;
}

// ---------------- k_pre: 208 blocks x 256 (2 subtiles) -------------------------
__global__ void __launch_bounds__(256) k_pre(const float* __restrict__ Wd1,
                                             const float* __restrict__ bd1,
                                             const float* __restrict__ Wd2,
                                             const float* __restrict__ bd2,
                                             const float* __restrict__ Wd3,
                                             const float* __restrict__ bd3,
                                             float* __restrict__ tab,
                                             const float* __restrict__ lf,
                                             const float* __restrict__ pf,
                                             const float* __restrict__ Wl,
                                             const float* __restrict__ bl,
                                             const float* __restrict__ Wp,
                                             const float* __restrict__ bp,
                                             float* __restrict__ lig,
                                             float* __restrict__ poc) {
    __shared__ __align__(16) float smem[2 * 2304];
    int tid = threadIdx.x;
    int sub = tid >> 7, st = tid & 127;
    int vb = blockIdx.x * 2 + sub;
    float* sbuf = smem + sub * 2304;
    float* w1s = sbuf + 2048;
    float* b1s = w1s + 32;
    float* b2s = b1s + 32;
    float* wms = b2s + 64;
    float* mcs = wms + 64;

    if (vb < 32) {
        for (int idx = st; idx < 2048; idx += 128) sbuf[idx] = Wd2[idx];
        if (st < 32) { w1s[st] = Wd1[st]; b1s[st] = bd1[st]; }
        if (st >= 32 && st < 96) b2s[st - 32] = bd2[st - 32];
        if (st < 64) {
            float s = 0.f;
            for (int i = 0; i < 128; i++) s += Wd3[i * 64 + st];
            wms[st] = s * (1.f / 128.f);
        }
        if (st == 127) {
            float s = 0.f;
            for (int i = 0; i < 128; i++) s += bd3[i];
            *mcs = s * (1.f / 128.f);
        }
        __syncthreads();
        int idx = vb * 128 + st;
        float d = (float)idx * (D_MAX / (float)(TAB_N - 1));
        float h1[32];
        #pragma unroll
        for (int k = 0; k < 32; k++) h1[k] = fmaxf(fmaf(d, w1s[k], b1s[k]), 0.f);
        float mval = *mcs;
        #pragma unroll 1
        for (int j = 0; j < 64; j++) {
            const float4* wr = (const float4*)(sbuf + j * 32);
            float a0 = 0.f, a1 = 0.f, a2 = 0.f, a3 = 0.f;
            #pragma unroll
            for (int q = 0; q < 8; q++) {
                float4 w = wr[q];
                a0 = fmaf(w.x, h1[4 * q + 0], a0);
                a1 = fmaf(w.y, h1[4 * q + 1], a1);
                a2 = fmaf(w.z, h1[4 * q + 2], a2);
                a3 = fmaf(w.w, h1[4 * q + 3], a3);
            }
            float pre = b2s[j] + ((a0 + a1) + (a2 + a3));
            mval = fmaf(fmaxf(pre, 0.f), wms[j], mval);
        }
        tab[idx] = mval;
    } else {
        int pb = vb - 32;
        const float* X; const float* W; const float* B; float* Y; int r0;
        if (pb < 128) { X = lf; W = Wl; B = bl; Y = lig; r0 = pb * 4; }
        else          { X = pf; W = Wp; B = bp; Y = poc; r0 = (pb - 128) * 4; }
        ((float4*)sbuf)[st] = ((const float4*)(X + (size_t)r0 * 128))[st];
        __syncthreads();
        const ulonglong2* X2 = (const ulonglong2*)sbuf;
        const ulonglong2* w2 = (const ulonglong2*)(W + (size_t)st * 128);
        unsigned long long acc2[4] = {0ull, 0ull, 0ull, 0ull};
        #pragma unroll 8
        for (int kb = 0; kb < 32; kb++) {
            ulonglong2 w = w2[kb];
            #pragma unroll
            for (int r = 0; r < 4; r++) {
                ulonglong2 x = X2[r * 32 + kb];
                acc2[r] = fma2(x.x, w.x, acc2[r]);
                acc2[r] = fma2(x.y, w.y, acc2[r]);
            }
        }
        float bv = B[st];
        #pragma unroll
        for (int r = 0; r < 4; r++)
            Y[(size_t)(r0 + r) * 128 + st] = hsum2(acc2[r]) + bv;
    }
}

// ---------------- aggsoft: inline pair-m + softmax + register-blocked GEMM ----
__global__ void __launch_bounds__(256) k_aggsoft(const float* __restrict__ lc,
                                                 const float* __restrict__ pc,
                                                 const float* __restrict__ tab,
                                                 const float* __restrict__ poc,
                                                 const float* __restrict__ lig,
                                                 float* __restrict__ aggl,
                                                 float* __restrict__ aggp) {
    extern __shared__ __align__(16) float dsm[];
    float* tabs = dsm;                // 4096
    float* cs   = dsm + TAB_N;        // 3072
    float* As   = dsm + TAB_N + 3072; // 8192
    int tid = threadIdx.x, bx = blockIdx.x;
    const float* B; float* Y; const float* own; const float* other; int r0, K;
    if (bx < 64) { B = poc; Y = aggl; own = lc; other = pc; r0 = bx * 8;        K = 1024; }
    else         { B = lig; Y = aggp; own = pc; other = lc; r0 = (bx - 64) * 8; K = 512;  }

    for (int idx = tid; idx < TAB_N; idx += 256) tabs[idx] = tab[idx];
    for (int idx = tid; idx < 3 * K; idx += 256) cs[idx] = other[idx];
    __syncthreads();

    int w = tid >> 5, lane = tid & 31;
    float ox = own[(r0 + w) * 3 + 0];
    float oy = own[(r0 + w) * 3 + 1];
    float oz = own[(r0 + w) * 3 + 2];
    const float invh = (float)(TAB_N - 1) / D_MAX;
    if (K == 1024) {
        float mv[32];
        float mx = -3.4e38f;
        #pragma unroll
        for (int t = 0; t < 32; t++) {
            int j = t * 32 + lane;
            float dx = ox - cs[j * 3 + 0];
            float dy = oy - cs[j * 3 + 1];
            float dz = oz - cs[j * 3 + 2];
            float d = sqrtf(fmaf(dx, dx, fmaf(dy, dy, dz * dz)));
            float tt = d * invh;
            int t0 = min((int)tt, TAB_N - 2);
            float f = tt - (float)t0;
            float v0 = tabs[t0], v1 = tabs[t0 + 1];
            float v = -fmaf(f, v1 - v0, v0);
            mv[t] = v;
            mx = fmaxf(mx, v);
        }
        #pragma unroll
        for (int o = 16; o > 0; o >>= 1)
            mx = fmaxf(mx, __shfl_xor_sync(0xffffffffu, mx, o));
        float sum = 0.f;
        #pragma unroll
        for (int t = 0; t < 32; t++) {
            float e = __expf(mv[t] - mx);
            mv[t] = e;
            sum += e;
        }
        #pragma unroll
        for (int o = 16; o > 0; o >>= 1)
            sum += __shfl_xor_sync(0xffffffffu, sum, o);
        float inv = 1.f / sum;
        #pragma unroll
        for (int t = 0; t < 32; t++) As[(t * 32 + lane) * 8 + w] = mv[t] * inv;
    } else {
        float mv[16];
        float mx = -3.4e38f;
        #pragma unroll
        for (int t = 0; t < 16; t++) {
            int j = t * 32 + lane;
            float dx = ox - cs[j * 3 + 0];
            float dy = oy - cs[j * 3 + 1];
            float dz = oz - cs[j * 3 + 2];
            float d = sqrtf(fmaf(dx, dx, fmaf(dy, dy, dz * dz)));
            float tt = d * invh;
            int t0 = min((int)tt, TAB_N - 2);
            float f = tt - (float)t0;
            float v0 = tabs[t0], v1 = tabs[t0 + 1];
            float v = -fmaf(f, v1 - v0, v0);
            mv[t] = v;
            mx = fmaxf(mx, v);
        }
        #pragma unroll
        for (int o = 16; o > 0; o >>= 1)
            mx = fmaxf(mx, __shfl_xor_sync(0xffffffffu, mx, o));
        float sum = 0.f;
        #pragma unroll
        for (int t = 0; t < 16; t++) {
            float e = __expf(mv[t] - mx);
            mv[t] = e;
            sum += e;
        }
        #pragma unroll
        for (int o = 16; o > 0; o >>= 1)
            sum += __shfl_xor_sync(0xffffffffu, sum, o);
        float inv = 1.f / sum;
        #pragma unroll
        for (int t = 0; t < 16; t++) As[(t * 32 + lane) * 8 + w] = mv[t] * inv;
    }
    __syncthreads();

    int cg = tid & 31, ks = tid >> 5;
    int steps = K >> 3;
    int kstart = ks * steps;
    float4 acc4[8];
    #pragma unroll
    for (int r = 0; r < 8; r++) acc4[r] = make_float4(0.f, 0.f, 0.f, 0.f);
    const float4* As4 = (const float4*)As;
    const float4* B4 = (const float4*)B;
    #pragma unroll 2
    for (int kk = 0; kk < steps; kk++) {
        int k = kstart + kk;
        float4 a0 = As4[k * 2 + 0];
        float4 a1 = As4[k * 2 + 1];
        float4 b = B4[(size_t)k * 32 + cg];
        acc4[0].x = fmaf(a0.x, b.x, acc4[0].x); acc4[0].y = fmaf(a0.x, b.y, acc4[0].y);
        acc4[0].z = fmaf(a0.x, b.z, acc4[0].z); acc4[0].w = fmaf(a0.x, b.w, acc4[0].w);
        acc4[1].x = fmaf(a0.y, b.x, acc4[1].x); acc4[1].y = fmaf(a0.y, b.y, acc4[1].y);
        acc4[1].z = fmaf(a0.y, b.z, acc4[1].z); acc4[1].w = fmaf(a0.y, b.w, acc4[1].w);
        acc4[2].x = fmaf(a0.z, b.x, acc4[2].x); acc4[2].y = fmaf(a0.z, b.y, acc4[2].y);
        acc4[2].z = fmaf(a0.z, b.z, acc4[2].z); acc4[2].w = fmaf(a0.z, b.w, acc4[2].w);
        acc4[3].x = fmaf(a0.w, b.x, acc4[3].x); acc4[3].y = fmaf(a0.w, b.y, acc4[3].y);
        acc4[3].z = fmaf(a0.w, b.z, acc4[3].z); acc4[3].w = fmaf(a0.w, b.w, acc4[3].w);
        acc4[4].x = fmaf(a1.x, b.x, acc4[4].x); acc4[4].y = fmaf(a1.x, b.y, acc4[4].y);
        acc4[4].z = fmaf(a1.x, b.z, acc4[4].z); acc4[4].w = fmaf(a1.x, b.w, acc4[4].w);
        acc4[5].x = fmaf(a1.y, b.x, acc4[5].x); acc4[5].y = fmaf(a1.y, b.y, acc4[5].y);
        acc4[5].z = fmaf(a1.y, b.z, acc4[5].z); acc4[5].w = fmaf(a1.y, b.w, acc4[5].w);
        acc4[6].x = fmaf(a1.z, b.x, acc4[6].x); acc4[6].y = fmaf(a1.z, b.y, acc4[6].y);
        acc4[6].z = fmaf(a1.z, b.z, acc4[6].z); acc4[6].w = fmaf(a1.z, b.w, acc4[6].w);
        acc4[7].x = fmaf(a1.w, b.x, acc4[7].x); acc4[7].y = fmaf(a1.w, b.y, acc4[7].y);
        acc4[7].z = fmaf(a1.w, b.z, acc4[7].z); acc4[7].w = fmaf(a1.w, b.w, acc4[7].w);
    }
    __syncthreads();
    float4* P4 = (float4*)As;
    #pragma unroll
    for (int r = 0; r < 8; r++) P4[ks * 256 + r * 32 + cg] = acc4[r];
    __syncthreads();
    float4 s = P4[tid];
    #pragma unroll
    for (int sl = 1; sl < 8; sl++) {
        float4 p = P4[sl * 256 + tid];
        s.x += p.x; s.y += p.y; s.z += p.z; s.w += p.w;
    }
    int r = tid >> 5, cc = tid & 31;
    ((float4*)(Y + (size_t)(r0 + r) * 128))[cc] = s;
}

// ---------------- gate: 192 blocks x 256, 8-row tiles, K split in halves ------
__global__ void __launch_bounds__(256) k_gate(const float* __restrict__ lig,
                                              const float* __restrict__ poc,
                                              const float* __restrict__ aggl,
                                              const float* __restrict__ aggp,
                                              const float* __restrict__ Wgl,
                                              const float* __restrict__ bgl,
                                              const float* __restrict__ Wgp,
                                              const float* __restrict__ bgp,
                                              float* __restrict__ lige,
                                              float* __restrict__ poce) {
    __shared__ __align__(16) float xs[1024];
    __shared__ __align__(16) float as_[1024];
    __shared__ float red[1024];
    int tid = threadIdx.x, vb = blockIdx.x;
    const float* X; const float* A; const float* W; const float* B;
    float* Y; int r0;
    if (vb < 64) { X = lig; A = aggl; W = Wgl; B = bgl; Y = lige; r0 = vb * 8; }
    else { X = poc; A = aggp; W = Wgp; B = bgp; Y = poce; r0 = (vb - 64) * 8; }
    ((float4*)xs)[tid] = ((const float4*)(X + (size_t)r0 * 128))[tid];
    ((float4*)as_)[tid] = ((const float4*)(A + (size_t)r0 * 128))[tid];
    __syncthreads();
    int c = tid & 127, part = tid >> 7;
    const ulonglong2* S2 = (const ulonglong2*)(part ? as_ : xs);
    const ulonglong2* w2 = (const ulonglong2*)(W + (size_t)c * 256 + part * 128);
    unsigned long long acc2[8];
    #pragma unroll
    for (int r = 0; r < 8; r++) acc2[r] = 0ull;
    #pragma unroll 8
    for (int kb = 0; kb < 32; kb++) {
        ulonglong2 w = w2[kb];
        #pragma unroll
        for (int r = 0; r < 8; r++) {
            ulonglong2 x = S2[r * 32 + kb];
            acc2[r] = fma2(x.x, w.x, acc2[r]);
            acc2[r] = fma2(x.y, w.y, acc2[r]);
        }
    }
    if (part) {
        #pragma unroll
        for (int r = 0; r < 8; r++) red[c * 8 + r] = hsum2(acc2[r]);
    }
    __syncthreads();
    if (!part) {
        float bv = B[c];
        #pragma unroll
        for (int r = 0; r < 8; r++) {
            float t = hsum2(acc2[r]) + red[c * 8 + r] + bv;
            float g = 1.f / (1.f + __expf(-t));
            float xv = xs[r * 128 + c], av = as_[r * 128 + c];
            Y[(size_t)(r0 + r) * 128 + c] = g * xv + (1.f - g) * av;
        }
    }
}

// ---------------- qkv v3: smem-staged weights, coalesced, f32x2 ----------------
// grid 288 (3 p x 96 tiles of 16 rows), block 256.
// Ws[kk][c] pad 129; Xp[k][rp] row-pair packed, pad 9.
__global__ void __launch_bounds__(256) k_qkv(const float* __restrict__ lige,
                                             const float* __restrict__ poce,
                                             const float* __restrict__ W,
                                             const float* __restrict__ B,
                                             float* __restrict__ qkvl,
                                             float* __restrict__ qkvp) {
    __shared__ __align__(16) float Ws[32 * 129];            // 16.5 KB
    __shared__ __align__(16) unsigned long long Xp[128 * 9]; // 9 KB (pad)
    int tid = threadIdx.x, vb = blockIdx.x;
    int p = vb / 96, tile = vb % 96;
    const float* X; float* Y; int r0;
    if (tile < 32) { X = lige; Y = qkvl; r0 = tile * 16; }
    else           { X = poce; Y = qkvp; r0 = (tile - 32) * 16; }

    // pack X rows into row-pairs: Xp[k*9 + rp] = (X[2rp][k], X[2rp+1][k])
    #pragma unroll
    for (int i = tid; i < 1024; i += 256) {
        int rp = i >> 7, k = i & 127;
        float x0 = X[(size_t)(r0 + 2 * rp) * 128 + k];
        float x1 = X[(size_t)(r0 + 2 * rp + 1) * 128 + k];
        Xp[k * 9 + rp] = pack2(x0, x1);
    }

    const float* Wp_ = W + (size_t)p * 128 * 128;  // this p's 128 output cols
    int c = tid & 127, half = tid >> 7;
    int rpb = half * 4;
    unsigned long long acc2[4] = {0ull, 0ull, 0ull, 0ull};

    #pragma unroll 1
    for (int chunk = 0; chunk < 4; chunk++) {
        __syncthreads();
        // stage 128 cols x 32 k, coalesced loads, transposed store
        #pragma unroll
        for (int it = 0; it < 4; it++) {
            int lin = it * 256 + tid;          // 0..1023 float4 units
            int cc = lin >> 3, q = lin & 7;
            float4 wv = *(const float4*)(Wp_ + (size_t)cc * 128 + chunk * 32 + q * 4);
            Ws[(q * 4 + 0) * 129 + cc] = wv.x;
            Ws[(q * 4 + 1) * 129 + cc] = wv.y;
            Ws[(q * 4 + 2) * 129 + cc] = wv.z;
            Ws[(q * 4 + 3) * 129 + cc] = wv.w;
        }
        __syncthreads();
        int kbase = chunk * 32;
        #pragma unroll 8
        for (int kk = 0; kk < 32; kk++) {
            float w = Ws[kk * 129 + c];
            unsigned long long w2 = pack2(w, w);
            const unsigned long long* xp = Xp + (kbase + kk) * 9 + rpb;
            acc2[0] = fma2(xp[0], w2, acc2[0]);
            acc2[1] = fma2(xp[1], w2, acc2[1]);
            acc2[2] = fma2(xp[2], w2, acc2[2]);
            acc2[3] = fma2(xp[3], w2, acc2[3]);
        }
    }

    int cglob = p * 128 + c;
    float bv = B[cglob];
    #pragma unroll
    for (int j = 0; j < 4; j++) {
        float x, y;
        unpack2(acc2[j], x, y);
        int rr = r0 + 2 * (rpb + j);
        Y[(size_t)rr * 384 + cglob] = x + bv;
        Y[(size_t)(rr + 1) * 384 + cglob] = y + bv;
    }
}

// ---------------- flash attention: 2 queries/warp, f32x2 AV --------------------
__global__ void __launch_bounds__(256) k_flash2(const float* __restrict__ qkvl,
                                                const float* __restrict__ qkvp,
                                                float* __restrict__ attl,
                                                float* __restrict__ attp) {
    __shared__ __align__(16) float4 Ks[128 * 5];
    __shared__ __align__(16) float4 Vs[128 * 5];
    int bx = blockIdx.x, h = blockIdx.y;
    int tid = threadIdx.x, w = tid >> 5, lane = tid & 31;
    const float* Qb; const float* KVb; float* outp; int nk, iA;
    if (bx < 32) { Qb = qkvl; KVb = qkvp; outp = attl; nk = 1024; iA = bx * 16 + w * 2; }
    else         { Qb = qkvp; KVb = qkvl; outp = attp; nk = 512; iA = (bx - 32) * 16 + w * 2; }

    const float* qpA = Qb + (size_t)iA * 384 + h * 16;
    float4 qA0 = ((const float4*)qpA)[0], qA1 = ((const float4*)qpA)[1];
    float4 qA2 = ((const float4*)qpA)[2], qA3 = ((const float4*)qpA)[3];
    const float* qpB = qpA + 384;
    float4 qB0 = ((const float4*)qpB)[0], qB1 = ((const float4*)qpB)[1];
    float4 qB2 = ((const float4*)qpB)[2], qB3 = ((const float4*)qpB)[3];

    float mA = -3.4e38f, lA = 0.f, mB = -3.4e38f, lB = 0.f;
    unsigned long long accA[8], accB[8];
    #pragma unroll
    for (int q = 0; q < 8; q++) { accA[q] = 0ull; accB[q] = 0ull; }

    int jload = tid >> 1, cl = (tid & 1) * 2;
    const float* kb0 = KVb + (size_t)jload * 384 + 128 + h * 16 + cl * 4;

    for (int jb = 0; jb < nk; jb += 128) {
        __syncthreads();
        const float* src = kb0 + (size_t)jb * 384;
        Ks[jload * 5 + cl]     = *(const float4*)(src);
        Ks[jload * 5 + cl + 1] = *(const float4*)(src + 4);
        Vs[jload * 5 + cl]     = *(const float4*)(src + 128);
        Vs[jload * 5 + cl + 1] = *(const float4*)(src + 132);
        __syncthreads();

        float sA[4], sB[4];
        #pragma unroll
        for (int jj = 0; jj < 4; jj++) {
            const float4* kr = Ks + (jj * 32 + lane) * 5;
            float4 k0 = kr[0], k1 = kr[1], k2 = kr[2], k3 = kr[3];
            float tA = qA0.x * k0.x;
            tA = fmaf(qA0.y, k0.y, tA); tA = fmaf(qA0.z, k0.z, tA); tA = fmaf(qA0.w, k0.w, tA);
            tA = fmaf(qA1.x, k1.x, tA); tA = fmaf(qA1.y, k1.y, tA);
            tA = fmaf(qA1.z, k1.z, tA); tA = fmaf(qA1.w, k1.w, tA);
            tA = fmaf(qA2.x, k2.x, tA); tA = fmaf(qA2.y, k2.y, tA);
            tA = fmaf(qA2.z, k2.z, tA); tA = fmaf(qA2.w, k2.w, tA);
            tA = fmaf(qA3.x, k3.x, tA); tA = fmaf(qA3.y, k3.y, tA);
            tA = fmaf(qA3.z, k3.z, tA); tA = fmaf(qA3.w, k3.w, tA);
            float tB = qB0.x * k0.x;
            tB = fmaf(qB0.y, k0.y, tB); tB = fmaf(qB0.z, k0.z, tB); tB = fmaf(qB0.w, k0.w, tB);
            tB = fmaf(qB1.x, k1.x, tB); tB = fmaf(qB1.y, k1.y, tB);
            tB = fmaf(qB1.z, k1.z, tB); tB = fmaf(qB1.w, k1.w, tB);
            tB = fmaf(qB2.x, k2.x, tB); tB = fmaf(qB2.y, k2.y, tB);
            tB = fmaf(qB2.z, k2.z, tB); tB = fmaf(qB2.w, k2.w, tB);
            tB = fmaf(qB3.x, k3.x, tB); tB = fmaf(qB3.y, k3.y, tB);
            tB = fmaf(qB3.z, k3.z, tB); tB = fmaf(qB3.w, k3.w, tB);
            sA[jj] = tA * 0.25f;
            sB[jj] = tB * 0.25f;
        }
        float txA = fmaxf(fmaxf(sA[0], sA[1]), fmaxf(sA[2], sA[3]));
        float txB = fmaxf(fmaxf(sB[0], sB[1]), fmaxf(sB[2], sB[3]));
        #pragma unroll
        for (int o = 16; o > 0; o >>= 1) {
            txA = fmaxf(txA, __shfl_xor_sync(0xffffffffu, txA, o));
            txB = fmaxf(txB, __shfl_xor_sync(0xffffffffu, txB, o));
        }
        float mnA = fmaxf(mA, txA), cA = __expf(mA - mnA);
        float mnB = fmaxf(mB, txB), cB = __expf(mB - mnB);
        mA = mnA; mB = mnB; lA *= cA; lB *= cB;
        unsigned long long cA2 = pack2(cA, cA), cB2 = pack2(cB, cB);
        #pragma unroll
        for (int q = 0; q < 8; q++) {
            accA[q] = mul2(accA[q], cA2);
            accB[q] = mul2(accB[q], cB2);
        }
        #pragma unroll
        for (int jj = 0; jj < 4; jj++) {
            float pA = __expf(sA[jj] - mA);
            float pB = __expf(sB[jj] - mB);
            lA += pA; lB += pB;
            unsigned long long pA2 = pack2(pA, pA), pB2 = pack2(pB, pB);
            const ulonglong2* vr = (const ulonglong2*)(Vs + (jj * 32 + lane) * 5);
            #pragma unroll
            for (int q = 0; q < 4; q++) {
                ulonglong2 v = vr[q];
                accA[q * 2]     = fma2(pA2, v.x, accA[q * 2]);
                accA[q * 2 + 1] = fma2(pA2, v.y, accA[q * 2 + 1]);
                accB[q * 2]     = fma2(pB2, v.x, accB[q * 2]);
                accB[q * 2 + 1] = fma2(pB2, v.y, accB[q * 2 + 1]);
            }
        }
    }

    #pragma unroll
    for (int o = 16; o > 0; o >>= 1) {
        lA += __shfl_xor_sync(0xffffffffu, lA, o);
        lB += __shfl_xor_sync(0xffffffffu, lB, o);
    }
    #pragma unroll
    for (int q = 0; q < 8; q++) {
        #pragma unroll
        for (int o = 16; o > 0; o >>= 1) {
            accA[q] = add2(accA[q], __shfl_xor_sync(0xffffffffu, accA[q], o));
            accB[q] = add2(accB[q], __shfl_xor_sync(0xffffffffu, accB[q], o));
        }
    }
    if (lane < 16) {
        float x, y;
        unpack2(accA[lane >> 1], x, y);
        float val = (lane & 1) ? y : x;
        outp[(size_t)iA * 128 + h * 16 + lane] = val * (1.f / lA);
    } else {
        int ll = lane - 16;
        float x, y;
        unpack2(accB[ll >> 1], x, y);
        float val = (ll & 1) ? y : x;
        outp[(size_t)(iA + 1) * 128 + h * 16 + ll] = val * (1.f / lB);
    }
}

// ---------------- out-proj + residual + LN: 192 blocks x 128, 8-row tiles -----
__global__ void __launch_bounds__(128) k_outln(const float* __restrict__ attl,
                                               const float* __restrict__ attp,
                                               const float* __restrict__ W,
                                               const float* __restrict__ bias,
                                               const float* __restrict__ lige,
                                               const float* __restrict__ poce,
                                               const float* __restrict__ g_l,
                                               const float* __restrict__ be_l,
                                               const float* __restrict__ g_p,
                                               const float* __restrict__ be_p,
                                               float* __restrict__ out) {
    __shared__ __align__(16) float Xs[1024];
    __shared__ __align__(16) float T[1024];
    __shared__ float mu[8], iv[8];
    int tid = threadIdx.x, vb = blockIdx.x;
    const float* X; const float* R; const float* gg; const float* bb;
    float* O; int r0;
    if (vb < 64) { X = attl; R = lige; gg = g_l; bb = be_l; O = out; r0 = vb * 8; }
    else {
        X = attp; R = poce; gg = g_p; bb = be_p;
        O = out + 512 * 128; r0 = (vb - 64) * 8;
    }
    ((float4*)Xs)[tid] = ((const float4*)(X + (size_t)r0 * 128))[tid];
    ((float4*)Xs)[tid + 128] = ((const float4*)(X + (size_t)r0 * 128))[tid + 128];
    __syncthreads();
    const ulonglong2* X2 = (const ulonglong2*)Xs;
    const ulonglong2* w2 = (const ulonglong2*)(W + (size_t)tid * 128);
    unsigned long long acc2[8] = {0ull, 0ull, 0ull, 0ull, 0ull, 0ull, 0ull, 0ull};
    #pragma unroll 4
    for (int kb = 0; kb < 32; kb++) {
        ulonglong2 w = w2[kb];
        #pragma unroll
        for (int r = 0; r < 8; r++) {
            ulonglong2 x = X2[r * 32 + kb];
            acc2[r] = fma2(x.x, w.x, acc2[r]);
            acc2[r] = fma2(x.y, w.y, acc2[r]);
        }
    }
    float bv = bias[tid];
    #pragma unroll
    for (int r = 0; r < 8; r++)
        T[r * 128 + tid] = hsum2(acc2[r]) + bv + R[(size_t)(r0 + r) * 128 + tid];
    __syncthreads();

    int wrp = tid >> 5, lane = tid & 31;
    #pragma unroll
    for (int rr = 0; rr < 2; rr++) {
        int r = wrp * 2 + rr;
        float t0 = T[r * 128 + lane], t1 = T[r * 128 + lane + 32];
        float t2 = T[r * 128 + lane + 64], t3 = T[r * 128 + lane + 96];
        float s = (t0 + t1) + (t2 + t3);
        #pragma unroll
        for (int o = 16; o > 0; o >>= 1) s += __shfl_xor_sync(0xffffffffu, s, o);
        float mean = s * (1.f / 128.f);
        float d0 = t0 - mean, d1 = t1 - mean, d2 = t2 - mean, d3 = t3 - mean;
        float v = (d0 * d0 + d1 * d1) + (d2 * d2 + d3 * d3);
        #pragma unroll
        for (int o = 16; o > 0; o >>= 1) v += __shfl_xor_sync(0xffffffffu, v, o);
        if (lane == 0) {
            mu[r] = mean;
            iv[r] = rsqrtf(v * (1.f / 128.f) + 1e-5f);
        }
    }
    __syncthreads();
    float gc = gg[tid], bc = bb[tid];
    #pragma unroll
    for (int r = 0; r < 8; r++) {
        float t = T[r * 128 + tid];
        O[(size_t)(r0 + r) * 128 + tid] = (t - mu[r]) * iv[r] * gc + bc;
    }
}

// ---------------- launch ------------------------------------------------------
extern "C" void kernel_launch(void* const* d_in, const int* in_sizes, int n_in,
                              void* d_out, int out_size) {
    const float* lf   = (const float*)d_in[0];
    const float* pf   = (const float*)d_in[1];
    const float* lc   = (const float*)d_in[2];
    const float* pc   = (const float*)d_in[3];
    const float* Wl   = (const float*)d_in[4];
    const float* bl   = (const float*)d_in[5];
    const float* Wp   = (const float*)d_in[6];
    const float* bp   = (const float*)d_in[7];
    const float* Wd1  = (const float*)d_in[8];
    const float* bd1  = (const float*)d_in[9];
    const float* Wd2  = (const float*)d_in[10];
    const float* bd2  = (const float*)d_in[11];
    const float* Wd3  = (const float*)d_in[12];
    const float* bd3  = (const float*)d_in[13];
    const float* Wgl  = (const float*)d_in[14];
    const float* bgl  = (const float*)d_in[15];
    const float* Wgp  = (const float*)d_in[16];
    const float* bgp  = (const float*)d_in[17];
    const float* Wqkv = (const float*)d_in[18];
    const float* bqkv = (const float*)d_in[19];
    const float* Wo   = (const float*)d_in[20];
    const float* bo   = (const float*)d_in[21];
    const float* g_l  = (const float*)d_in[22];
    const float* be_l = (const float*)d_in[23];
    const float* g_p  = (const float*)d_in[24];
    const float* be_p = (const float*)d_in[25];
    float* out = (float*)d_out;

    float* SB = nullptr;
    cudaGetSymbolAddress((void**)&SB, g_scratch);
    float* s_lig  = SB + OFF_LIG;
    float* s_poc  = SB + OFF_POC;
    float* s_aggl = SB + OFF_AGGL;
    float* s_aggp = SB + OFF_AGGP;
    float* s_lige = SB + OFF_LIGE;
    float* s_poce = SB + OFF_POCE;
    float* s_qkvl = SB + OFF_QKVL;
    float* s_qkvp = SB + OFF_QKVP;
    float* s_attl = SB + OFF_ATTL;
    float* s_attp = SB + OFF_ATTP;
    float* s_tab  = SB + OFF_TAB;

    static bool s_attr_set = false;
    if (!s_attr_set) {
        cudaFuncSetAttribute(k_aggsoft,
                             cudaFuncAttributeMaxDynamicSharedMemorySize,
                             (TAB_N + 3072 + 8192) * 4);
        s_attr_set = true;
    }

    k_pre<<<208, 256>>>(Wd1, bd1, Wd2, bd2, Wd3, bd3, s_tab,
                        lf, pf, Wl, bl, Wp, bp, s_lig, s_poc);
    k_aggsoft<<<192, 256, (TAB_N + 3072 + 8192) * 4>>>(lc, pc, s_tab, s_poc,
                                                       s_lig, s_aggl, s_aggp);
    k_gate<<<192, 256>>>(s_lig, s_poc, s_aggl, s_aggp, Wgl, bgl, Wgp, bgp,
                         s_lige, s_poce);
    k_qkv<<<288, 256>>>(s_lige, s_poce, Wqkv, bqkv, s_qkvl, s_qkvp);
    k_flash2<<<dim3(96, 8), 256>>>(s_qkvl, s_qkvp, s_attl, s_attp);
    k_outln<<<192, 128>>>(s_attl, s_attp, Wo, bo, s_lige, s_poce,
                          g_l, be_l, g_p, be_p, out);
}

// round 17
// speedup vs baseline: 1.1831x; 1.0132x over previous
#include <cuda_runtime.h>
#include <math.h>

// ---------------- scratch (device globals; no allocation allowed) ----------
#define OFF_LIG     0           // 512*128
#define OFF_POC     65536       // 1024*128
#define OFF_AGGL    196608      // 512*128
#define OFF_AGGP    262144      // 1024*128
#define OFF_LIGE    393216      // 512*128
#define OFF_POCE    458752      // 1024*128
#define OFF_QKVL    589824      // 512*384
#define OFF_QKVP    786432      // 1024*384
#define OFF_ATTL    1179648     // 512*128
#define OFF_ATTP    1245184     // 1024*128
#define OFF_TAB     1376256     // 4096
#define SCRATCH_FLOATS 1380352

__device__ float g_scratch[SCRATCH_FLOATS];

#define TAB_N 4096
#define D_MAX 35.0f

// ---------------- f32x2 helpers ----------------------------------------------
__device__ __forceinline__ unsigned long long fma2(unsigned long long a,
                                                   unsigned long long b,
                                                   unsigned long long c) {
    unsigned long long d;
    asm("fma.rn.f32x2 %0, %1, %2, %3;" : "=l"(d) : "l"(a), "l"(b), "l"(c));
    return d;
}
__device__ __forceinline__ unsigned long long mul2(unsigned long long a,
                                                   unsigned long long b) {
    unsigned long long d;
    asm("mul.rn.f32x2 %0, %1, %2;" : "=l"(d) : "l"(a), "l"(b));
    return d;
}
__device__ __forceinline__ unsigned long long add2(unsigned long long a,
                                                   unsigned long long b) {
    unsigned long long d;
    asm("add.rn.f32x2 %0, %1, %2;" : "=l"(d) : "l"(a), "l"(b));
    return d;
}
__device__ __forceinline__ unsigned long long pack2(float x, float y) {
    unsigned long long r;
    asm("mov.b64 %0, {%1, %2};" : "=l"(r) : "f"(x), "f"(y));
    return r;
}
__device__ __forceinline__ void unpack2(unsigned long long v, float& x, float& y) {
    asm("mov.b64 {%0, %1}, %2;" : "=f"(x), "=f"(y) : "l"(v));
}
__device__ __forceinline__ float hsum2(unsigned long long v) {
    float x, y;
    unpack2(v, x, y);
    return x + y;
}

// ---------------- k_pre: 208 blocks x 256 (2 subtiles) -------------------------
__global__ void __launch_bounds__(256) k_pre(const float* __restrict__ Wd1,
                                             const float* __restrict__ bd1,
                                             const float* __restrict__ Wd2,
                                             const float* __restrict__ bd2,
                                             const float* __restrict__ Wd3,
                                             const float* __restrict__ bd3,
                                             float* __restrict__ tab,
                                             const float* __restrict__ lf,
                                             const float* __restrict__ pf,
                                             const float* __restrict__ Wl,
                                             const float* __restrict__ bl,
                                             const float* __restrict__ Wp,
                                             const float* __restrict__ bp,
                                             float* __restrict__ lig,
                                             float* __restrict__ poc) {
    __shared__ __align__(16) float smem[2 * 2304];
    int tid = threadIdx.x;
    int sub = tid >> 7, st = tid & 127;
    int vb = blockIdx.x * 2 + sub;
    float* sbuf = smem + sub * 2304;
    float* w1s = sbuf + 2048;
    float* b1s = w1s + 32;
    float* b2s = b1s + 32;
    float* wms = b2s + 64;
    float* mcs = wms + 64;

    if (vb < 32) {
        for (int idx = st; idx < 2048; idx += 128) sbuf[idx] = Wd2[idx];
        if (st < 32) { w1s[st] = Wd1[st]; b1s[st] = bd1[st]; }
        if (st >= 32 && st < 96) b2s[st - 32] = bd2[st - 32];
        if (st < 64) {
            float s = 0.f;
            for (int i = 0; i < 128; i++) s += Wd3[i * 64 + st];
            wms[st] = s * (1.f / 128.f);
        }
        if (st == 127) {
            float s = 0.f;
            for (int i = 0; i < 128; i++) s += bd3[i];
            *mcs = s * (1.f / 128.f);
        }
        __syncthreads();
        int idx = vb * 128 + st;
        float d = (float)idx * (D_MAX / (float)(TAB_N - 1));
        float h1[32];
        #pragma unroll
        for (int k = 0; k < 32; k++) h1[k] = fmaxf(fmaf(d, w1s[k], b1s[k]), 0.f);
        float mval = *mcs;
        #pragma unroll 1
        for (int j = 0; j < 64; j++) {
            const float4* wr = (const float4*)(sbuf + j * 32);
            float a0 = 0.f, a1 = 0.f, a2 = 0.f, a3 = 0.f;
            #pragma unroll
            for (int q = 0; q < 8; q++) {
                float4 w = wr[q];
                a0 = fmaf(w.x, h1[4 * q + 0], a0);
                a1 = fmaf(w.y, h1[4 * q + 1], a1);
                a2 = fmaf(w.z, h1[4 * q + 2], a2);
                a3 = fmaf(w.w, h1[4 * q + 3], a3);
            }
            float pre = b2s[j] + ((a0 + a1) + (a2 + a3));
            mval = fmaf(fmaxf(pre, 0.f), wms[j], mval);
        }
        tab[idx] = mval;
    } else {
        int pb = vb - 32;
        const float* X; const float* W; const float* B; float* Y; int r0;
        if (pb < 128) { X = lf; W = Wl; B = bl; Y = lig; r0 = pb * 4; }
        else          { X = pf; W = Wp; B = bp; Y = poc; r0 = (pb - 128) * 4; }
        ((float4*)sbuf)[st] = ((const float4*)(X + (size_t)r0 * 128))[st];
        __syncthreads();
        const ulonglong2* X2 = (const ulonglong2*)sbuf;
        const ulonglong2* w2 = (const ulonglong2*)(W + (size_t)st * 128);
        unsigned long long acc2[4] = {0ull, 0ull, 0ull, 0ull};
        #pragma unroll 8
        for (int kb = 0; kb < 32; kb++) {
            ulonglong2 w = w2[kb];
            #pragma unroll
            for (int r = 0; r < 4; r++) {
                ulonglong2 x = X2[r * 32 + kb];
                acc2[r] = fma2(x.x, w.x, acc2[r]);
                acc2[r] = fma2(x.y, w.y, acc2[r]);
            }
        }
        float bv = B[st];
        #pragma unroll
        for (int r = 0; r < 4; r++)
            Y[(size_t)(r0 + r) * 128 + st] = hsum2(acc2[r]) + bv;
    }
}

// ---------------- aggsoft: inline pair-m + softmax + register-blocked GEMM ----
__global__ void __launch_bounds__(256) k_aggsoft(const float* __restrict__ lc,
                                                 const float* __restrict__ pc,
                                                 const float* __restrict__ tab,
                                                 const float* __restrict__ poc,
                                                 const float* __restrict__ lig,
                                                 float* __restrict__ aggl,
                                                 float* __restrict__ aggp) {
    extern __shared__ __align__(16) float dsm[];
    float* tabs = dsm;                // 4096
    float* cs   = dsm + TAB_N;        // 3072
    float* As   = dsm + TAB_N + 3072; // 8192
    int tid = threadIdx.x, bx = blockIdx.x;
    const float* B; float* Y; const float* own; const float* other; int r0, K;
    if (bx < 64) { B = poc; Y = aggl; own = lc; other = pc; r0 = bx * 8;        K = 1024; }
    else         { B = lig; Y = aggp; own = pc; other = lc; r0 = (bx - 64) * 8; K = 512;  }

    for (int idx = tid; idx < TAB_N; idx += 256) tabs[idx] = tab[idx];
    for (int idx = tid; idx < 3 * K; idx += 256) cs[idx] = other[idx];
    __syncthreads();

    int w = tid >> 5, lane = tid & 31;
    float ox = own[(r0 + w) * 3 + 0];
    float oy = own[(r0 + w) * 3 + 1];
    float oz = own[(r0 + w) * 3 + 2];
    const float invh = (float)(TAB_N - 1) / D_MAX;
    if (K == 1024) {
        float mv[32];
        float mx = -3.4e38f;
        #pragma unroll
        for (int t = 0; t < 32; t++) {
            int j = t * 32 + lane;
            float dx = ox - cs[j * 3 + 0];
            float dy = oy - cs[j * 3 + 1];
            float dz = oz - cs[j * 3 + 2];
            float d = sqrtf(fmaf(dx, dx, fmaf(dy, dy, dz * dz)));
            float tt = d * invh;
            int t0 = min((int)tt, TAB_N - 2);
            float f = tt - (float)t0;
            float v0 = tabs[t0], v1 = tabs[t0 + 1];
            float v = -fmaf(f, v1 - v0, v0);
            mv[t] = v;
            mx = fmaxf(mx, v);
        }
        #pragma unroll
        for (int o = 16; o > 0; o >>= 1)
            mx = fmaxf(mx, __shfl_xor_sync(0xffffffffu, mx, o));
        float sum = 0.f;
        #pragma unroll
        for (int t = 0; t < 32; t++) {
            float e = __expf(mv[t] - mx);
            mv[t] = e;
            sum += e;
        }
        #pragma unroll
        for (int o = 16; o > 0; o >>= 1)
            sum += __shfl_xor_sync(0xffffffffu, sum, o);
        float inv = 1.f / sum;
        #pragma unroll
        for (int t = 0; t < 32; t++) As[(t * 32 + lane) * 8 + w] = mv[t] * inv;
    } else {
        float mv[16];
        float mx = -3.4e38f;
        #pragma unroll
        for (int t = 0; t < 16; t++) {
            int j = t * 32 + lane;
            float dx = ox - cs[j * 3 + 0];
            float dy = oy - cs[j * 3 + 1];
            float dz = oz - cs[j * 3 + 2];
            float d = sqrtf(fmaf(dx, dx, fmaf(dy, dy, dz * dz)));
            float tt = d * invh;
            int t0 = min((int)tt, TAB_N - 2);
            float f = tt - (float)t0;
            float v0 = tabs[t0], v1 = tabs[t0 + 1];
            float v = -fmaf(f, v1 - v0, v0);
            mv[t] = v;
            mx = fmaxf(mx, v);
        }
        #pragma unroll
        for (int o = 16; o > 0; o >>= 1)
            mx = fmaxf(mx, __shfl_xor_sync(0xffffffffu, mx, o));
        float sum = 0.f;
        #pragma unroll
        for (int t = 0; t < 16; t++) {
            float e = __expf(mv[t] - mx);
            mv[t] = e;
            sum += e;
        }
        #pragma unroll
        for (int o = 16; o > 0; o >>= 1)
            sum += __shfl_xor_sync(0xffffffffu, sum, o);
        float inv = 1.f / sum;
        #pragma unroll
        for (int t = 0; t < 16; t++) As[(t * 32 + lane) * 8 + w] = mv[t] * inv;
    }
    __syncthreads();

    int cg = tid & 31, ks = tid >> 5;
    int steps = K >> 3;
    int kstart = ks * steps;
    float4 acc4[8];
    #pragma unroll
    for (int r = 0; r < 8; r++) acc4[r] = make_float4(0.f, 0.f, 0.f, 0.f);
    const float4* As4 = (const float4*)As;
    const float4* B4 = (const float4*)B;
    #pragma unroll 2
    for (int kk = 0; kk < steps; kk++) {
        int k = kstart + kk;
        float4 a0 = As4[k * 2 + 0];
        float4 a1 = As4[k * 2 + 1];
        float4 b = B4[(size_t)k * 32 + cg];
        acc4[0].x = fmaf(a0.x, b.x, acc4[0].x); acc4[0].y = fmaf(a0.x, b.y, acc4[0].y);
        acc4[0].z = fmaf(a0.x, b.z, acc4[0].z); acc4[0].w = fmaf(a0.x, b.w, acc4[0].w);
        acc4[1].x = fmaf(a0.y, b.x, acc4[1].x); acc4[1].y = fmaf(a0.y, b.y, acc4[1].y);
        acc4[1].z = fmaf(a0.y, b.z, acc4[1].z); acc4[1].w = fmaf(a0.y, b.w, acc4[1].w);
        acc4[2].x = fmaf(a0.z, b.x, acc4[2].x); acc4[2].y = fmaf(a0.z, b.y, acc4[2].y);
        acc4[2].z = fmaf(a0.z, b.z, acc4[2].z); acc4[2].w = fmaf(a0.z, b.w, acc4[2].w);
        acc4[3].x = fmaf(a0.w, b.x, acc4[3].x); acc4[3].y = fmaf(a0.w, b.y, acc4[3].y);
        acc4[3].z = fmaf(a0.w, b.z, acc4[3].z); acc4[3].w = fmaf(a0.w, b.w, acc4[3].w);
        acc4[4].x = fmaf(a1.x, b.x, acc4[4].x); acc4[4].y = fmaf(a1.x, b.y, acc4[4].y);
        acc4[4].z = fmaf(a1.x, b.z, acc4[4].z); acc4[4].w = fmaf(a1.x, b.w, acc4[4].w);
        acc4[5].x = fmaf(a1.y, b.x, acc4[5].x); acc4[5].y = fmaf(a1.y, b.y, acc4[5].y);
        acc4[5].z = fmaf(a1.y, b.z, acc4[5].z); acc4[5].w = fmaf(a1.y, b.w, acc4[5].w);
        acc4[6].x = fmaf(a1.z, b.x, acc4[6].x); acc4[6].y = fmaf(a1.z, b.y, acc4[6].y);
        acc4[6].z = fmaf(a1.z, b.z, acc4[6].z); acc4[6].w = fmaf(a1.z, b.w, acc4[6].w);
        acc4[7].x = fmaf(a1.w, b.x, acc4[7].x); acc4[7].y = fmaf(a1.w, b.y, acc4[7].y);
        acc4[7].z = fmaf(a1.w, b.z, acc4[7].z); acc4[7].w = fmaf(a1.w, b.w, acc4[7].w);
    }
    __syncthreads();
    float4* P4 = (float4*)As;
    #pragma unroll
    for (int r = 0; r < 8; r++) P4[ks * 256 + r * 32 + cg] = acc4[r];
    __syncthreads();
    float4 s = P4[tid];
    #pragma unroll
    for (int sl = 1; sl < 8; sl++) {
        float4 p = P4[sl * 256 + tid];
        s.x += p.x; s.y += p.y; s.z += p.z; s.w += p.w;
    }
    int r = tid >> 5, cc = tid & 31;
    ((float4*)(Y + (size_t)(r0 + r) * 128))[cc] = s;
}

// ---------------- gate v2: smem-staged weights, f32x2 row pairs ----------------
// grid 192 (8-row tiles), block 256. Xp packs x (k<128) and agg (k>=128).
__global__ void __launch_bounds__(256) k_gate(const float* __restrict__ lig,
                                              const float* __restrict__ poc,
                                              const float* __restrict__ aggl,
                                              const float* __restrict__ aggp,
                                              const float* __restrict__ Wgl,
                                              const float* __restrict__ bgl,
                                              const float* __restrict__ Wgp,
                                              const float* __restrict__ bgp,
                                              float* __restrict__ lige,
                                              float* __restrict__ poce) {
    __shared__ __align__(16) float Ws[32 * 129];             // 16.5 KB
    __shared__ __align__(16) unsigned long long Xp[256 * 5]; // 10 KB
    int tid = threadIdx.x, vb = blockIdx.x;
    const float* X; const float* A; const float* W; const float* B;
    float* Y; int r0;
    if (vb < 64) { X = lig; A = aggl; W = Wgl; B = bgl; Y = lige; r0 = vb * 8; }
    else { X = poc; A = aggp; W = Wgp; B = bgp; Y = poce; r0 = (vb - 64) * 8; }

    // pack x|agg row pairs: Xp[k*5+rp] = (S[2rp][k'], S[2rp+1][k'])
    for (int i = tid; i < 1024; i += 256) {
        int rp = i >> 8, k = i & 255;
        const float* S = (k < 128) ? X : A;
        int kk = k & 127;
        float v0 = S[(size_t)(r0 + 2 * rp) * 128 + kk];
        float v1 = S[(size_t)(r0 + 2 * rp + 1) * 128 + kk];
        Xp[k * 5 + rp] = pack2(v0, v1);
    }

    int c = tid & 127, half = tid >> 7, rpb = half * 2;
    unsigned long long acc2[2] = {0ull, 0ull};
    #pragma unroll 1
    for (int ch = 0; ch < 8; ch++) {
        __syncthreads();
        #pragma unroll
        for (int it = 0; it < 4; it++) {
            int lin = it * 256 + tid;
            int cc = lin >> 3, q = lin & 7;
            float4 wv = *(const float4*)(W + (size_t)cc * 256 + ch * 32 + q * 4);
            Ws[(q * 4 + 0) * 129 + cc] = wv.x;
            Ws[(q * 4 + 1) * 129 + cc] = wv.y;
            Ws[(q * 4 + 2) * 129 + cc] = wv.z;
            Ws[(q * 4 + 3) * 129 + cc] = wv.w;
        }
        __syncthreads();
        int kbase = ch * 32;
        #pragma unroll 8
        for (int kk = 0; kk < 32; kk++) {
            float w = Ws[kk * 129 + c];
            unsigned long long w2 = pack2(w, w);
            const unsigned long long* xp = Xp + (kbase + kk) * 5 + rpb;
            acc2[0] = fma2(xp[0], w2, acc2[0]);
            acc2[1] = fma2(xp[1], w2, acc2[1]);
        }
    }

    float bv = B[c];
    #pragma unroll
    for (int j = 0; j < 2; j++) {
        float t0, t1;
        unpack2(acc2[j], t0, t1);
        int rp = rpb + j;
        float x0, x1, a0, a1;
        unpack2(Xp[c * 5 + rp], x0, x1);
        unpack2(Xp[(128 + c) * 5 + rp], a0, a1);
        float g0 = 1.f / (1.f + __expf(-(t0 + bv)));
        float g1 = 1.f / (1.f + __expf(-(t1 + bv)));
        Y[(size_t)(r0 + 2 * rp) * 128 + c]     = g0 * x0 + (1.f - g0) * a0;
        Y[(size_t)(r0 + 2 * rp + 1) * 128 + c] = g1 * x1 + (1.f - g1) * a1;
    }
}

// ---------------- qkv v3: smem-staged weights, coalesced, f32x2 ----------------
__global__ void __launch_bounds__(256) k_qkv(const float* __restrict__ lige,
                                             const float* __restrict__ poce,
                                             const float* __restrict__ W,
                                             const float* __restrict__ B,
                                             float* __restrict__ qkvl,
                                             float* __restrict__ qkvp) {
    __shared__ __align__(16) float Ws[32 * 129];
    __shared__ __align__(16) unsigned long long Xp[128 * 9];
    int tid = threadIdx.x, vb = blockIdx.x;
    int p = vb / 96, tile = vb % 96;
    const float* X; float* Y; int r0;
    if (tile < 32) { X = lige; Y = qkvl; r0 = tile * 16; }
    else           { X = poce; Y = qkvp; r0 = (tile - 32) * 16; }

    #pragma unroll
    for (int i = tid; i < 1024; i += 256) {
        int rp = i >> 7, k = i & 127;
        float x0 = X[(size_t)(r0 + 2 * rp) * 128 + k];
        float x1 = X[(size_t)(r0 + 2 * rp + 1) * 128 + k];
        Xp[k * 9 + rp] = pack2(x0, x1);
    }

    const float* Wp_ = W + (size_t)p * 128 * 128;
    int c = tid & 127, half = tid >> 7;
    int rpb = half * 4;
    unsigned long long acc2[4] = {0ull, 0ull, 0ull, 0ull};

    #pragma unroll 1
    for (int chunk = 0; chunk < 4; chunk++) {
        __syncthreads();
        #pragma unroll
        for (int it = 0; it < 4; it++) {
            int lin = it * 256 + tid;
            int cc = lin >> 3, q = lin & 7;
            float4 wv = *(const float4*)(Wp_ + (size_t)cc * 128 + chunk * 32 + q * 4);
            Ws[(q * 4 + 0) * 129 + cc] = wv.x;
            Ws[(q * 4 + 1) * 129 + cc] = wv.y;
            Ws[(q * 4 + 2) * 129 + cc] = wv.z;
            Ws[(q * 4 + 3) * 129 + cc] = wv.w;
        }
        __syncthreads();
        int kbase = chunk * 32;
        #pragma unroll 8
        for (int kk = 0; kk < 32; kk++) {
            float w = Ws[kk * 129 + c];
            unsigned long long w2 = pack2(w, w);
            const unsigned long long* xp = Xp + (kbase + kk) * 9 + rpb;
            acc2[0] = fma2(xp[0], w2, acc2[0]);
            acc2[1] = fma2(xp[1], w2, acc2[1]);
            acc2[2] = fma2(xp[2], w2, acc2[2]);
            acc2[3] = fma2(xp[3], w2, acc2[3]);
        }
    }

    int cglob = p * 128 + c;
    float bv = B[cglob];
    #pragma unroll
    for (int j = 0; j < 4; j++) {
        float x, y;
        unpack2(acc2[j], x, y);
        int rr = r0 + 2 * (rpb + j);
        Y[(size_t)rr * 384 + cglob] = x + bv;
        Y[(size_t)(rr + 1) * 384 + cglob] = y + bv;
    }
}

// ---------------- flash attention: 2 queries/warp, f32x2 AV --------------------
__global__ void __launch_bounds__(256) k_flash2(const float* __restrict__ qkvl,
                                                const float* __restrict__ qkvp,
                                                float* __restrict__ attl,
                                                float* __restrict__ attp) {
    __shared__ __align__(16) float4 Ks[128 * 5];
    __shared__ __align__(16) float4 Vs[128 * 5];
    int bx = blockIdx.x, h = blockIdx.y;
    int tid = threadIdx.x, w = tid >> 5, lane = tid & 31;
    const float* Qb; const float* KVb; float* outp; int nk, iA;
    if (bx < 32) { Qb = qkvl; KVb = qkvp; outp = attl; nk = 1024; iA = bx * 16 + w * 2; }
    else         { Qb = qkvp; KVb = qkvl; outp = attp; nk = 512; iA = (bx - 32) * 16 + w * 2; }

    const float* qpA = Qb + (size_t)iA * 384 + h * 16;
    float4 qA0 = ((const float4*)qpA)[0], qA1 = ((const float4*)qpA)[1];
    float4 qA2 = ((const float4*)qpA)[2], qA3 = ((const float4*)qpA)[3];
    const float* qpB = qpA + 384;
    float4 qB0 = ((const float4*)qpB)[0], qB1 = ((const float4*)qpB)[1];
    float4 qB2 = ((const float4*)qpB)[2], qB3 = ((const float4*)qpB)[3];

    float mA = -3.4e38f, lA = 0.f, mB = -3.4e38f, lB = 0.f;
    unsigned long long accA[8], accB[8];
    #pragma unroll
    for (int q = 0; q < 8; q++) { accA[q] = 0ull; accB[q] = 0ull; }

    int jload = tid >> 1, cl = (tid & 1) * 2;
    const float* kb0 = KVb + (size_t)jload * 384 + 128 + h * 16 + cl * 4;

    for (int jb = 0; jb < nk; jb += 128) {
        __syncthreads();
        const float* src = kb0 + (size_t)jb * 384;
        Ks[jload * 5 + cl]     = *(const float4*)(src);
        Ks[jload * 5 + cl + 1] = *(const float4*)(src + 4);
        Vs[jload * 5 + cl]     = *(const float4*)(src + 128);
        Vs[jload * 5 + cl + 1] = *(const float4*)(src + 132);
        __syncthreads();

        float sA[4], sB[4];
        #pragma unroll
        for (int jj = 0; jj < 4; jj++) {
            const float4* kr = Ks + (jj * 32 + lane) * 5;
            float4 k0 = kr[0], k1 = kr[1], k2 = kr[2], k3 = kr[3];
            float tA = qA0.x * k0.x;
            tA = fmaf(qA0.y, k0.y, tA); tA = fmaf(qA0.z, k0.z, tA); tA = fmaf(qA0.w, k0.w, tA);
            tA = fmaf(qA1.x, k1.x, tA); tA = fmaf(qA1.y, k1.y, tA);
            tA = fmaf(qA1.z, k1.z, tA); tA = fmaf(qA1.w, k1.w, tA);
            tA = fmaf(qA2.x, k2.x, tA); tA = fmaf(qA2.y, k2.y, tA);
            tA = fmaf(qA2.z, k2.z, tA); tA = fmaf(qA2.w, k2.w, tA);
            tA = fmaf(qA3.x, k3.x, tA); tA = fmaf(qA3.y, k3.y, tA);
            tA = fmaf(qA3.z, k3.z, tA); tA = fmaf(qA3.w, k3.w, tA);
            float tB = qB0.x * k0.x;
            tB = fmaf(qB0.y, k0.y, tB); tB = fmaf(qB0.z, k0.z, tB); tB = fmaf(qB0.w, k0.w, tB);
            tB = fmaf(qB1.x, k1.x, tB); tB = fmaf(qB1.y, k1.y, tB);
            tB = fmaf(qB1.z, k1.z, tB); tB = fmaf(qB1.w, k1.w, tB);
            tB = fmaf(qB2.x, k2.x, tB); tB = fmaf(qB2.y, k2.y, tB);
            tB = fmaf(qB2.z, k2.z, tB); tB = fmaf(qB2.w, k2.w, tB);
            tB = fmaf(qB3.x, k3.x, tB); tB = fmaf(qB3.y, k3.y, tB);
            tB = fmaf(qB3.z, k3.z, tB); tB = fmaf(qB3.w, k3.w, tB);
            sA[jj] = tA * 0.25f;
            sB[jj] = tB * 0.25f;
        }
        float txA = fmaxf(fmaxf(sA[0], sA[1]), fmaxf(sA[2], sA[3]));
        float txB = fmaxf(fmaxf(sB[0], sB[1]), fmaxf(sB[2], sB[3]));
        #pragma unroll
        for (int o = 16; o > 0; o >>= 1) {
            txA = fmaxf(txA, __shfl_xor_sync(0xffffffffu, txA, o));
            txB = fmaxf(txB, __shfl_xor_sync(0xffffffffu, txB, o));
        }
        float mnA = fmaxf(mA, txA), cA = __expf(mA - mnA);
        float mnB = fmaxf(mB, txB), cB = __expf(mB - mnB);
        mA = mnA; mB = mnB; lA *= cA; lB *= cB;
        unsigned long long cA2 = pack2(cA, cA), cB2 = pack2(cB, cB);
        #pragma unroll
        for (int q = 0; q < 8; q++) {
            accA[q] = mul2(accA[q], cA2);
            accB[q] = mul2(accB[q], cB2);
        }
        #pragma unroll
        for (int jj = 0; jj < 4; jj++) {
            float pA = __expf(sA[jj] - mA);
            float pB = __expf(sB[jj] - mB);
            lA += pA; lB += pB;
            unsigned long long pA2 = pack2(pA, pA), pB2 = pack2(pB, pB);
            const ulonglong2* vr = (const ulonglong2*)(Vs + (jj * 32 + lane) * 5);
            #pragma unroll
            for (int q = 0; q < 4; q++) {
                ulonglong2 v = vr[q];
                accA[q * 2]     = fma2(pA2, v.x, accA[q * 2]);
                accA[q * 2 + 1] = fma2(pA2, v.y, accA[q * 2 + 1]);
                accB[q * 2]     = fma2(pB2, v.x, accB[q * 2]);
                accB[q * 2 + 1] = fma2(pB2, v.y, accB[q * 2 + 1]);
            }
        }
    }

    #pragma unroll
    for (int o = 16; o > 0; o >>= 1) {
        lA += __shfl_xor_sync(0xffffffffu, lA, o);
        lB += __shfl_xor_sync(0xffffffffu, lB, o);
    }
    #pragma unroll
    for (int q = 0; q < 8; q++) {
        #pragma unroll
        for (int o = 16; o > 0; o >>= 1) {
            accA[q] = add2(accA[q], __shfl_xor_sync(0xffffffffu, accA[q], o));
            accB[q] = add2(accB[q], __shfl_xor_sync(0xffffffffu, accB[q], o));
        }
    }
    if (lane < 16) {
        float x, y;
        unpack2(accA[lane >> 1], x, y);
        float val = (lane & 1) ? y : x;
        outp[(size_t)iA * 128 + h * 16 + lane] = val * (1.f / lA);
    } else {
        int ll = lane - 16;
        float x, y;
        unpack2(accB[ll >> 1], x, y);
        float val = (ll & 1) ? y : x;
        outp[(size_t)(iA + 1) * 128 + h * 16 + ll] = val * (1.f / lB);
    }
}

// ---------------- outln v2: smem-staged weights + residual + LN ---------------
// grid 192 (8-row tiles), block 256.
__global__ void __launch_bounds__(256) k_outln(const float* __restrict__ attl,
                                               const float* __restrict__ attp,
                                               const float* __restrict__ W,
                                               const float* __restrict__ bias,
                                               const float* __restrict__ lige,
                                               const float* __restrict__ poce,
                                               const float* __restrict__ g_l,
                                               const float* __restrict__ be_l,
                                               const float* __restrict__ g_p,
                                               const float* __restrict__ be_p,
                                               float* __restrict__ out) {
    __shared__ __align__(16) float Ws[32 * 129];             // 16.5 KB
    __shared__ __align__(16) unsigned long long Xp[128 * 5]; // 5 KB
    __shared__ __align__(16) float T[1024];
    __shared__ float mu[8], iv[8];
    int tid = threadIdx.x, vb = blockIdx.x;
    const float* X; const float* R; const float* gg; const float* bb;
    float* O; int r0;
    if (vb < 64) { X = attl; R = lige; gg = g_l; bb = be_l; O = out; r0 = vb * 8; }
    else {
        X = attp; R = poce; gg = g_p; bb = be_p;
        O = out + 512 * 128; r0 = (vb - 64) * 8;
    }

    for (int i = tid; i < 512; i += 256) {
        int rp = i >> 7, k = i & 127;
        float v0 = X[(size_t)(r0 + 2 * rp) * 128 + k];
        float v1 = X[(size_t)(r0 + 2 * rp + 1) * 128 + k];
        Xp[k * 5 + rp] = pack2(v0, v1);
    }

    int c = tid & 127, half = tid >> 7, rpb = half * 2;
    unsigned long long acc2[2] = {0ull, 0ull};
    #pragma unroll 1
    for (int ch = 0; ch < 4; ch++) {
        __syncthreads();
        #pragma unroll
        for (int it = 0; it < 4; it++) {
            int lin = it * 256 + tid;
            int cc = lin >> 3, q = lin & 7;
            float4 wv = *(const float4*)(W + (size_t)cc * 128 + ch * 32 + q * 4);
            Ws[(q * 4 + 0) * 129 + cc] = wv.x;
            Ws[(q * 4 + 1) * 129 + cc] = wv.y;
            Ws[(q * 4 + 2) * 129 + cc] = wv.z;
            Ws[(q * 4 + 3) * 129 + cc] = wv.w;
        }
        __syncthreads();
        int kbase = ch * 32;
        #pragma unroll 8
        for (int kk = 0; kk < 32; kk++) {
            float w = Ws[kk * 129 + c];
            unsigned long long w2 = pack2(w, w);
            const unsigned long long* xp = Xp + (kbase + kk) * 5 + rpb;
            acc2[0] = fma2(xp[0], w2, acc2[0]);
            acc2[1] = fma2(xp[1], w2, acc2[1]);
        }
    }

    float bv = bias[c];
    #pragma unroll
    for (int j = 0; j < 2; j++) {
        float t0, t1;
        unpack2(acc2[j], t0, t1);
        int rr = 2 * (rpb + j);
        T[rr * 128 + c]       = t0 + bv + R[(size_t)(r0 + rr) * 128 + c];
        T[(rr + 1) * 128 + c] = t1 + bv + R[(size_t)(r0 + rr + 1) * 128 + c];
    }
    __syncthreads();

    // LN stats: warp per row (8 warps)
    int w = tid >> 5, lane = tid & 31;
    {
        float t0 = T[w * 128 + lane], t1 = T[w * 128 + lane + 32];
        float t2 = T[w * 128 + lane + 64], t3 = T[w * 128 + lane + 96];
        float s = (t0 + t1) + (t2 + t3);
        #pragma unroll
        for (int o = 16; o > 0; o >>= 1) s += __shfl_xor_sync(0xffffffffu, s, o);
        float mean = s * (1.f / 128.f);
        float d0 = t0 - mean, d1 = t1 - mean, d2 = t2 - mean, d3 = t3 - mean;
        float v = (d0 * d0 + d1 * d1) + (d2 * d2 + d3 * d3);
        #pragma unroll
        for (int o = 16; o > 0; o >>= 1) v += __shfl_xor_sync(0xffffffffu, v, o);
        if (lane == 0) {
            mu[w] = mean;
            iv[w] = rsqrtf(v * (1.f / 128.f) + 1e-5f);
        }
    }
    __syncthreads();
    for (int i = tid; i < 1024; i += 256) {
        int r = i >> 7, cc = i & 127;
        O[(size_t)(r0 + r) * 128 + cc] = (T[i] - mu[r]) * iv[r] * gg[cc] + bb[cc];
    }
}

// ---------------- launch ------------------------------------------------------
extern "C" void kernel_launch(void* const* d_in, const int* in_sizes, int n_in,
                              void* d_out, int out_size) {
    const float* lf   = (const float*)d_in[0];
    const float* pf   = (const float*)d_in[1];
    const float* lc   = (const float*)d_in[2];
    const float* pc   = (const float*)d_in[3];
    const float* Wl   = (const float*)d_in[4];
    const float* bl   = (const float*)d_in[5];
    const float* Wp   = (const float*)d_in[6];
    const float* bp   = (const float*)d_in[7];
    const float* Wd1  = (const float*)d_in[8];
    const float* bd1  = (const float*)d_in[9];
    const float* Wd2  = (const float*)d_in[10];
    const float* bd2  = (const float*)d_in[11];
    const float* Wd3  = (const float*)d_in[12];
    const float* bd3  = (const float*)d_in[13];
    const float* Wgl  = (const float*)d_in[14];
    const float* bgl  = (const float*)d_in[15];
    const float* Wgp  = (const float*)d_in[16];
    const float* bgp  = (const float*)d_in[17];
    const float* Wqkv = (const float*)d_in[18];
    const float* bqkv = (const float*)d_in[19];
    const float* Wo   = (const float*)d_in[20];
    const float* bo   = (const float*)d_in[21];
    const float* g_l  = (const float*)d_in[22];
    const float* be_l = (const float*)d_in[23];
    const float* g_p  = (const float*)d_in[24];
    const float* be_p = (const float*)d_in[25];
    float* out = (float*)d_out;

    float* SB = nullptr;
    cudaGetSymbolAddress((void**)&SB, g_scratch);
    float* s_lig  = SB + OFF_LIG;
    float* s_poc  = SB + OFF_POC;
    float* s_aggl = SB + OFF_AGGL;
    float* s_aggp = SB + OFF_AGGP;
    float* s_lige = SB + OFF_LIGE;
    float* s_poce = SB + OFF_POCE;
    float* s_qkvl = SB + OFF_QKVL;
    float* s_qkvp = SB + OFF_QKVP;
    float* s_attl = SB + OFF_ATTL;
    float* s_attp = SB + OFF_ATTP;
    float* s_tab  = SB + OFF_TAB;

    static bool s_attr_set = false;
    if (!s_attr_set) {
        cudaFuncSetAttribute(k_aggsoft,
                             cudaFuncAttributeMaxDynamicSharedMemorySize,
                             (TAB_N + 3072 + 8192) * 4);
        s_attr_set = true;
    }

    k_pre<<<208, 256>>>(Wd1, bd1, Wd2, bd2, Wd3, bd3, s_tab,
                        lf, pf, Wl, bl, Wp, bp, s_lig, s_poc);
    k_aggsoft<<<192, 256, (TAB_N + 3072 + 8192) * 4>>>(lc, pc, s_tab, s_poc,
                                                       s_lig, s_aggl, s_aggp);
    k_gate<<<192, 256>>>(s_lig, s_poc, s_aggl, s_aggp, Wgl, bgl, Wgp, bgp,
                         s_lige, s_poce);
    k_qkv<<<288, 256>>>(s_lige, s_poce, Wqkv, bqkv, s_qkvl, s_qkvp);
    k_flash2<<<dim3(96, 8), 256>>>(s_qkvl, s_qkvp, s_attl, s_attp);
    k_outln<<<192, 256>>>(s_attl, s_attp, Wo, bo, s_lige, s_poce,
                          g_l, be_l, g_p, be_p, out);
}